// round 12
// baseline (speedup 1.0000x reference)
#include <cuda_runtime.h>
#include <cuda_fp16.h>
#include <math.h>
#include <stdint.h>

#define T_TOK 1024
#define H_DIM 2048
#define I_DIM 768
#define E_NUM 32
#define K_TOP 8

#define BM 128
#define BN 64
#define BK 32            // k-floats per slab (fp16 row = 64B)
#define RSB 80           // fp16 smem row stride bytes (conflict-free ldmatrix)
#define STAGES 4         // A-only cp.async stages

#define A_STG   (BM * RSB)                  // 10240 B per A stage
#define GU_DEST (STAGES * A_STG)            // B fp16 dest (2 buffers x 128 rows)
#define GU_DBUF (2 * BN * RSB)              // 10240 per buffer (gate 0..63, up 64..127)
#define GU_SMEM (GU_DEST + 2 * GU_DBUF)     // 61440 -> 2 CTAs/SM

#define DN_DEST (STAGES * A_STG)
#define DN_DBUF (BN * RSB)                  // 5120 per buffer
#define DN_SMEM (DN_DEST + 2 * DN_DBUF)     // 51200 -> 2 CTAs/SM

#define GU_NC (H_DIM / BK)                  // 64
#define DN_NC (I_DIM / BK)                  // 24

// ---------------- scratch ----------------
__device__ int    g_cnt[E_NUM];
__device__ int    g_off[E_NUM + 1];
__device__ int    g_list_tok[E_NUM * T_TOK];
__device__ float  g_list_w[E_NUM * T_TOK];
__device__ int    g_list_tk[E_NUM * T_TOK];
__device__ int    g_slot_of[T_TOK * K_TOP];
__device__ __half g_act[(size_t)T_TOK * K_TOP * I_DIM];
__device__ float  g_pair[(size_t)T_TOK * K_TOP * H_DIM];
__device__ __half g_xh[(size_t)T_TOK * H_DIM];

// ---------------- x fp32->fp16 + zero counters ----------------
__global__ void convert_x_kernel(const float* __restrict__ x) {
    if (blockIdx.x == 0 && threadIdx.x < E_NUM) g_cnt[threadIdx.x] = 0;
    const size_t NX = (size_t)T_TOK * H_DIM / 4;
    size_t stride = (size_t)gridDim.x * blockDim.x;
    for (size_t i = (size_t)blockIdx.x * blockDim.x + threadIdx.x; i < NX; i += stride) {
        float4 v = ((const float4*)x)[i];
        __half2 h[2];
        h[0] = __floats2half2_rn(v.x, v.y);
        h[1] = __floats2half2_rn(v.z, v.w);
        *(uint2*)(g_xh + i * 4) = *(uint2*)h;
    }
}

// ---------------- router ----------------
__global__ void router_kernel(const float* __restrict__ x,
                              const float* __restrict__ gate_w,
                              float* __restrict__ logits_out) {
    const int TPB = 4;
    __shared__ float xs[TPB][H_DIM];
    __shared__ float lg[TPB][E_NUM];

    int t0 = blockIdx.x * TPB;
    const float4* xv  = (const float4*)(x + (size_t)t0 * H_DIM);
    float4*       xsv = (float4*)&xs[0][0];
    for (int i = threadIdx.x; i < TPB * H_DIM / 4; i += blockDim.x) xsv[i] = xv[i];
    __syncthreads();

    int warp = threadIdx.x >> 5;
    int lane = threadIdx.x & 31;

    for (int sub = 0; sub < 4; sub++) {
        int e = warp + sub * 8;
        const float* w = gate_w + (size_t)e * H_DIM;
        float p0 = 0.f, p1 = 0.f, p2 = 0.f, p3 = 0.f;
        for (int h = lane; h < H_DIM; h += 32) {
            float wv = w[h];
            p0 += xs[0][h] * wv;
            p1 += xs[1][h] * wv;
            p2 += xs[2][h] * wv;
            p3 += xs[3][h] * wv;
        }
        for (int o = 16; o; o >>= 1) {
            p0 += __shfl_xor_sync(0xFFFFFFFFu, p0, o);
            p1 += __shfl_xor_sync(0xFFFFFFFFu, p1, o);
            p2 += __shfl_xor_sync(0xFFFFFFFFu, p2, o);
            p3 += __shfl_xor_sync(0xFFFFFFFFu, p3, o);
        }
        if (lane == 0) { lg[0][e] = p0; lg[1][e] = p1; lg[2][e] = p2; lg[3][e] = p3; }
    }
    __syncthreads();

    if (warp < TPB) {
        int t = t0 + warp;
        float logit = lg[warp][lane];
        if (logits_out) logits_out[(size_t)t * E_NUM + lane] = logit;

        float m = logit;
        for (int o = 16; o; o >>= 1) m = fmaxf(m, __shfl_xor_sync(0xFFFFFFFFu, m, o));
        float ex = expf(logit - m);
        float s = ex;
        for (int o = 16; o; o >>= 1) s += __shfl_xor_sync(0xFFFFFFFFu, s, o);
        float prob = ex / s;

        float v = prob;
        float wsum = 0.f;
        float selw[K_TOP];
        int   sele[K_TOP];
#pragma unroll
        for (int k = 0; k < K_TOP; k++) {
            float mv = v;
            for (int o = 16; o; o >>= 1) mv = fmaxf(mv, __shfl_xor_sync(0xFFFFFFFFu, mv, o));
            unsigned msk = __ballot_sync(0xFFFFFFFFu, v == mv);
            int src = __ffs(msk) - 1;
            if (lane == 0) { sele[k] = src; selw[k] = mv; wsum += mv; }
            if (lane == src) v = -1.f;
        }
        if (lane == 0) {
#pragma unroll
            for (int k = 0; k < K_TOP; k++) {
                int e = sele[k];
                float wn = selw[k] / wsum;
                int pos = atomicAdd(&g_cnt[e], 1);
                g_list_tok[e * T_TOK + pos] = t;
                g_list_w[e * T_TOK + pos]   = wn;
                g_list_tk[e * T_TOK + pos]  = t * K_TOP + k;
            }
        }
    }
}

// ---------------- fused scan + remap ----------------
__global__ void scan_remap_kernel() {
    if (threadIdx.x == 0) {
        int acc = 0;
        for (int e = 0; e < E_NUM; e++) { g_off[e] = acc; acc += g_cnt[e]; }
        g_off[E_NUM] = acc;
    }
    __syncthreads();
    for (int e = 0; e < E_NUM; e++) {
        int n = g_cnt[e], o = g_off[e];
        for (int p = threadIdx.x; p < n; p += blockDim.x)
            g_slot_of[g_list_tk[e * T_TOK + p]] = o + p;
    }
}

__device__ __forceinline__ float silu_f(float g) { return g / (1.f + expf(-g)); }

__device__ __forceinline__ uint32_t smem_u32(const void* p) {
    uint32_t a;
    asm("{ .reg .u64 t; cvta.to.shared.u64 t, %1; cvt.u32.u64 %0, t; }" : "=r"(a) : "l"(p));
    return a;
}

#define LDM4(r0, r1, r2, r3, addr) \
    asm volatile("ldmatrix.sync.aligned.m8n8.x4.shared.b16 {%0,%1,%2,%3}, [%4];" \
                 : "=r"(r0), "=r"(r1), "=r"(r2), "=r"(r3) : "r"(addr))

#define CP16(dst, src) \
    asm volatile("cp.async.cg.shared.global [%0], [%1], 16;" :: "r"(dst), "l"(src) : "memory")
#define CP_COMMIT() asm volatile("cp.async.commit_group;" ::: "memory")
#define CP_WAIT(n)  asm volatile("cp.async.wait_group %0;" :: "n"(n) : "memory")

__device__ __forceinline__ void mma16(float* c, uint32_t a0, uint32_t a1, uint32_t a2, uint32_t a3,
                                      uint32_t b0, uint32_t b1) {
    asm volatile("mma.sync.aligned.m16n8k16.row.col.f32.f16.f16.f32 "
                 "{%0,%1,%2,%3}, {%4,%5,%6,%7}, {%8,%9}, {%0,%1,%2,%3};"
                 : "+f"(c[0]), "+f"(c[1]), "+f"(c[2]), "+f"(c[3])
                 : "r"(a0), "r"(a1), "r"(a2), "r"(a3), "r"(b0), "r"(b1));
}

// cvt 8 fp32 (2x float4) -> 16B fp16 STS.128
__device__ __forceinline__ void cvt_sts(unsigned char* dst, float4 v0, float4 v1) {
    __half2 h[4];
    h[0] = __floats2half2_rn(v0.x, v0.y);
    h[1] = __floats2half2_rn(v0.z, v0.w);
    h[2] = __floats2half2_rn(v1.x, v1.y);
    h[3] = __floats2half2_rn(v1.z, v1.w);
    *(uint4*)dst = *(uint4*)h;
}

extern __shared__ unsigned char dsm[];

// ---------------- grouped gate+up GEMM ----------------
// A: fp16 cp.async 4-stage. B: fp32 LDG -> reg cvt -> STS fp16, double-buffered dest.
__global__ __launch_bounds__(256, 2) void gateup_kernel(const float* __restrict__ gw,
                                                        const float* __restrict__ uw) {
    int e  = blockIdx.z;
    int n  = g_cnt[e];
    int m0 = blockIdx.x * BM;
    if (m0 >= n) return;
    int c0 = blockIdx.y * BN;

    uint32_t sbase = smem_u32(dsm);
    int tid  = threadIdx.x;
    int lane = tid & 31;
    int warp = tid >> 5;
    int wM = warp & 3;
    int wN = warp >> 2;

    // A loader (cp.async): 2 threads per row, 32 B per slab per thread
    int lr = tid >> 1;
    int hf = tid & 1;
    int tokA = g_list_tok[e * T_TOK + min(m0 + lr, n - 1)];
    const __half* pA = g_xh + (size_t)tokA * H_DIM + hf * 16;
    uint32_t soA = lr * RSB + hf * 32;

    // B loader (LDG fp32): chunk c = tid + 256j (j=0,1); row = c>>2 (0..127), 32B piece (c&3)
    const float* pB[2];
    uint32_t soBd[2];     // offset within dest buffer
#pragma unroll
    for (int j = 0; j < 2; j++) {
        int c = tid + 256 * j;
        int row = c >> 2;                  // <64 gate, >=64 up
        const float* base = (row < 64)
            ? gw + ((size_t)e * I_DIM + (c0 + row)) * H_DIM
            : uw + ((size_t)e * I_DIM + (c0 + row - 64)) * H_DIM;
        pB[j]   = base + (c & 3) * 8;      // 8 floats = 32B
        soBd[j] = row * RSB + (c & 3) * 16;
    }

    int mat = lane >> 3, rr = lane & 7;
    uint32_t aBase[2], bgBase[2], buBase[2];
#pragma unroll
    for (int mi = 0; mi < 2; mi++)
        aBase[mi] = sbase + (uint32_t)((wM * 32 + mi * 16 + (mat & 1) * 8 + rr) * RSB + (mat >> 1) * 16);
#pragma unroll
    for (int p = 0; p < 2; p++) {
        uint32_t roff = (uint32_t)((wN * 32 + p * 16 + (mat >> 1) * 8 + rr) * RSB + (mat & 1) * 16);
        bgBase[p] = sbase + GU_DEST + roff;            // gate rows 0..63
        buBase[p] = sbase + GU_DEST + 64 * RSB + roff; // up rows 64..127
    }

    float cg[2][4][4] = {};
    float cu[2][4][4] = {};

#define GU_A_ISSUE(i)                                                     \
    { uint32_t bb = ((i) & (STAGES - 1)) * A_STG;                         \
      const __half* sa = pA + (i) * 32;                                   \
      CP16(sbase + bb + soA, sa); CP16(sbase + bb + soA + 16, sa + 8); }

    GU_A_ISSUE(0); CP_COMMIT();
    GU_A_ISSUE(1); CP_COMMIT();
    GU_A_ISSUE(2); CP_COMMIT();

    // B slab 0 -> dest buffer 0 (visible after first top-of-loop sync)
    {
        float4 v0a = *(const float4*)(pB[0]);
        float4 v0b = *(const float4*)(pB[0] + 4);
        float4 v1a = *(const float4*)(pB[1]);
        float4 v1b = *(const float4*)(pB[1] + 4);
        cvt_sts(dsm + GU_DEST + soBd[0], v0a, v0b);
        cvt_sts(dsm + GU_DEST + soBd[1], v1a, v1b);
    }

    for (int i = 0; i < GU_NC; i++) {
        CP_WAIT(STAGES - 2);
        __syncthreads();
        uint32_t ast = (i & (STAGES - 1)) * A_STG;
        uint32_t dst = (i & 1) * GU_DBUF;

        bool pre = (i + 1 < GU_NC);
        float4 nb0a, nb0b, nb1a, nb1b;
        if (pre) {
            const float* q0 = pB[0] + (i + 1) * 32;
            const float* q1 = pB[1] + (i + 1) * 32;
            nb0a = *(const float4*)(q0); nb0b = *(const float4*)(q0 + 4);
            nb1a = *(const float4*)(q1); nb1b = *(const float4*)(q1 + 4);
        }

#pragma unroll
        for (int ks = 0; ks < 2; ks++) {
            uint32_t af[2][4];
#pragma unroll
            for (int mi = 0; mi < 2; mi++)
                LDM4(af[mi][0], af[mi][1], af[mi][2], af[mi][3], aBase[mi] + ast + ks * 32);
            uint32_t gf[2][4], uf[2][4];
#pragma unroll
            for (int p = 0; p < 2; p++) {
                LDM4(gf[p][0], gf[p][1], gf[p][2], gf[p][3], bgBase[p] + dst + ks * 32);
                LDM4(uf[p][0], uf[p][1], uf[p][2], uf[p][3], buBase[p] + dst + ks * 32);
            }
#pragma unroll
            for (int t = 0; t < 4; t++) {
                int p = t >> 1, q = (t & 1) * 2;
#pragma unroll
                for (int mi = 0; mi < 2; mi++) {
                    mma16(cg[mi][t], af[mi][0], af[mi][1], af[mi][2], af[mi][3], gf[p][q], gf[p][q + 1]);
                    mma16(cu[mi][t], af[mi][0], af[mi][1], af[mi][2], af[mi][3], uf[p][q], uf[p][q + 1]);
                }
            }
        }

        if (pre) {
            uint32_t nd = GU_DEST + ((i + 1) & 1) * GU_DBUF;
            cvt_sts(dsm + nd + soBd[0], nb0a, nb0b);
            cvt_sts(dsm + nd + soBd[1], nb1a, nb1b);
        }
        if (i + STAGES - 1 < GU_NC) GU_A_ISSUE(i + STAGES - 1);
        CP_COMMIT();
    }
#undef GU_A_ISSUE

    // ---- epilogue ----
    int off = g_off[e];
    int g  = lane >> 2;
    int tq = lane & 3;
#pragma unroll
    for (int mi = 0; mi < 2; mi++) {
        int r0 = m0 + wM * 32 + mi * 16 + g;
        int r1 = r0 + 8;
        float w0 = (r0 < n) ? g_list_w[e * T_TOK + r0] : 0.f;
        float w1 = (r1 < n) ? g_list_w[e * T_TOK + r1] : 0.f;
#pragma unroll
        for (int t = 0; t < 4; t++) {
            int col = c0 + wN * 32 + t * 8 + 2 * tq;
            if (r0 < n) {
                float ox = silu_f(cg[mi][t][0]) * cu[mi][t][0] * w0;
                float oy = silu_f(cg[mi][t][1]) * cu[mi][t][1] * w0;
                *(__half2*)&g_act[((size_t)(off + r0)) * I_DIM + col] = __floats2half2_rn(ox, oy);
            }
            if (r1 < n) {
                float ox = silu_f(cg[mi][t][2]) * cu[mi][t][2] * w1;
                float oy = silu_f(cg[mi][t][3]) * cu[mi][t][3] * w1;
                *(__half2*)&g_act[((size_t)(off + r1)) * I_DIM + col] = __floats2half2_rn(ox, oy);
            }
        }
    }
}

// ---------------- grouped down GEMM ----------------
__global__ __launch_bounds__(256, 2) void down_kernel(const float* __restrict__ dw) {
    int e  = blockIdx.z;
    int n  = g_cnt[e];
    int m0 = blockIdx.x * BM;
    if (m0 >= n) return;
    int c0  = blockIdx.y * BN;
    int off = g_off[e];

    uint32_t sbase = smem_u32(dsm);
    int tid  = threadIdx.x;
    int lane = tid & 31;
    int warp = tid >> 5;
    int wM = warp & 3;
    int wN = warp >> 2;

    int lr = tid >> 1;
    int hf = tid & 1;
    const __half* pA = g_act + (size_t)(off + min(m0 + lr, n - 1)) * I_DIM + hf * 16;
    uint32_t soA = lr * RSB + hf * 32;

    // B loader: chunk c = tid; row = c>>2 (0..63)
    int row = tid >> 2;
    const float* pB = dw + ((size_t)e * H_DIM + (c0 + row)) * I_DIM + (tid & 3) * 8;
    uint32_t soBd = row * RSB + (tid & 3) * 16;

    int mat = lane >> 3, rr = lane & 7;
    uint32_t aBase[2], bBase[2];
#pragma unroll
    for (int mi = 0; mi < 2; mi++)
        aBase[mi] = sbase + (uint32_t)((wM * 32 + mi * 16 + (mat & 1) * 8 + rr) * RSB + (mat >> 1) * 16);
#pragma unroll
    for (int p = 0; p < 2; p++)
        bBase[p] = sbase + DN_DEST + (uint32_t)((wN * 32 + p * 16 + (mat >> 1) * 8 + rr) * RSB + (mat & 1) * 16);

    float c[2][4][4] = {};

#define DN_A_ISSUE(i)                                                     \
    { uint32_t bb = ((i) & (STAGES - 1)) * A_STG;                         \
      const __half* sa = pA + (i) * 32;                                   \
      CP16(sbase + bb + soA, sa); CP16(sbase + bb + soA + 16, sa + 8); }

    DN_A_ISSUE(0); CP_COMMIT();
    DN_A_ISSUE(1); CP_COMMIT();
    DN_A_ISSUE(2); CP_COMMIT();

    {
        float4 v0 = *(const float4*)(pB);
        float4 v1 = *(const float4*)(pB + 4);
        cvt_sts(dsm + DN_DEST + soBd, v0, v1);
    }

    for (int i = 0; i < DN_NC; i++) {
        CP_WAIT(STAGES - 2);
        __syncthreads();
        uint32_t ast = (i & (STAGES - 1)) * A_STG;
        uint32_t dst = (i & 1) * DN_DBUF;

        bool pre = (i + 1 < DN_NC);
        float4 nb0, nb1;
        if (pre) {
            const float* q = pB + (i + 1) * 32;
            nb0 = *(const float4*)(q); nb1 = *(const float4*)(q + 4);
        }

#pragma unroll
        for (int ks = 0; ks < 2; ks++) {
            uint32_t af[2][4];
#pragma unroll
            for (int mi = 0; mi < 2; mi++)
                LDM4(af[mi][0], af[mi][1], af[mi][2], af[mi][3], aBase[mi] + ast + ks * 32);
            uint32_t bf[2][4];
#pragma unroll
            for (int p = 0; p < 2; p++)
                LDM4(bf[p][0], bf[p][1], bf[p][2], bf[p][3], bBase[p] + dst + ks * 32);
#pragma unroll
            for (int t = 0; t < 4; t++) {
                int p = t >> 1, q = (t & 1) * 2;
#pragma unroll
                for (int mi = 0; mi < 2; mi++)
                    mma16(c[mi][t], af[mi][0], af[mi][1], af[mi][2], af[mi][3], bf[p][q], bf[p][q + 1]);
            }
        }

        if (pre) {
            uint32_t nd = DN_DEST + ((i + 1) & 1) * DN_DBUF;
            cvt_sts(dsm + nd + soBd, nb0, nb1);
        }
        if (i + STAGES - 1 < DN_NC) DN_A_ISSUE(i + STAGES - 1);
        CP_COMMIT();
    }
#undef DN_A_ISSUE

    int g  = lane >> 2;
    int tq = lane & 3;
#pragma unroll
    for (int mi = 0; mi < 2; mi++) {
        int r0 = m0 + wM * 32 + mi * 16 + g;
        int r1 = r0 + 8;
#pragma unroll
        for (int t = 0; t < 4; t++) {
            int col = c0 + wN * 32 + t * 8 + 2 * tq;
            if (r0 < n) {
                float2 o = make_float2(c[mi][t][0], c[mi][t][1]);
                *(float2*)&g_pair[((size_t)(off + r0)) * H_DIM + col] = o;
            }
            if (r1 < n) {
                float2 o = make_float2(c[mi][t][2], c[mi][t][3]);
                *(float2*)&g_pair[((size_t)(off + r1)) * H_DIM + col] = o;
            }
        }
    }
}

// ---------------- per-token reduction ----------------
__global__ void reduce_kernel(float* __restrict__ out) {
    int t = blockIdx.x;
    int s[K_TOP];
#pragma unroll
    for (int k = 0; k < K_TOP; k++) s[k] = g_slot_of[t * K_TOP + k];
    const float4* base = (const float4*)g_pair;
    float4* ob = (float4*)(out + (size_t)t * H_DIM);
    for (int i = threadIdx.x; i < H_DIM / 4; i += blockDim.x) {
        float4 acc = make_float4(0.f, 0.f, 0.f, 0.f);
#pragma unroll
        for (int k = 0; k < K_TOP; k++) {
            float4 v = base[(size_t)s[k] * (H_DIM / 4) + i];
            acc.x += v.x; acc.y += v.y; acc.z += v.z; acc.w += v.w;
        }
        ob[i] = acc;
    }
}

// ---------------- launch ----------------
extern "C" void kernel_launch(void* const* d_in, const int* in_sizes, int n_in,
                              void* d_out, int out_size) {
    const float* x      = (const float*)d_in[0];
    const float* gate_w = (const float*)d_in[1];
    const float* gw     = (const float*)d_in[2];
    const float* uw     = (const float*)d_in[3];
    const float* dw     = (const float*)d_in[4];
    float* out = (float*)d_out;

    float* logits = (out_size >= T_TOK * H_DIM + T_TOK * E_NUM) ? (out + (size_t)T_TOK * H_DIM)
                                                                : (float*)0;

    cudaFuncSetAttribute(gateup_kernel, cudaFuncAttributeMaxDynamicSharedMemorySize, GU_SMEM);
    cudaFuncSetAttribute(down_kernel,   cudaFuncAttributeMaxDynamicSharedMemorySize, DN_SMEM);

    convert_x_kernel<<<256, 256>>>(x);
    router_kernel<<<T_TOK / 4, 256>>>(x, gate_w, logits);
    scan_remap_kernel<<<1, 256>>>();
    gateup_kernel<<<dim3(T_TOK / BM, I_DIM / BN, E_NUM), 256, GU_SMEM>>>(gw, uw);
    down_kernel<<<dim3(T_TOK / BM, H_DIM / BN, E_NUM), 256, DN_SMEM>>>(dw);
    reduce_kernel<<<T_TOK, 256>>>(out);
}

// round 13
// speedup vs baseline: 1.1542x; 1.1542x over previous
#include <cuda_runtime.h>
#include <cuda_fp16.h>
#include <math.h>
#include <stdint.h>

#define T_TOK 1024
#define H_DIM 2048
#define I_DIM 768
#define E_NUM 32
#define K_TOP 8

#define BM 128
#define BN 64            // gateup N tile
#define DN_BN 128        // down N tile (2x reuse of A fragments)
#define BK 32            // k-floats per slab (fp16 row = 64B)
#define RSB 80           // fp16 smem row stride bytes (conflict-free ldmatrix)
#define STAGES 4         // A-only cp.async stages

#define A_STG   (BM * RSB)                  // 10240 B per A stage
#define GU_DEST (STAGES * A_STG)            // B fp16 dest (2 buffers x 128 rows)
#define GU_DBUF (2 * BN * RSB)              // 10240 per buffer (gate 0..63, up 64..127)
#define GU_SMEM (GU_DEST + 2 * GU_DBUF)     // 61440 -> 2 CTAs/SM

#define DN_DEST (STAGES * A_STG)
#define DN_DBUF (DN_BN * RSB)               // 10240 per buffer
#define DN_SMEM (DN_DEST + 2 * DN_DBUF)     // 61440 -> 2 CTAs/SM

#define GU_NC (H_DIM / BK)                  // 64
#define DN_NC (I_DIM / BK)                  // 24

// ---------------- scratch ----------------
__device__ int    g_cnt[E_NUM];
__device__ int    g_off[E_NUM + 1];
__device__ int    g_list_tok[E_NUM * T_TOK];
__device__ float  g_list_w[E_NUM * T_TOK];
__device__ int    g_list_tk[E_NUM * T_TOK];
__device__ int    g_slot_of[T_TOK * K_TOP];
__device__ __half g_act[(size_t)T_TOK * K_TOP * I_DIM];
__device__ float  g_pair[(size_t)T_TOK * K_TOP * H_DIM];
__device__ __half g_xh[(size_t)T_TOK * H_DIM];

// ---------------- x fp32->fp16 + zero counters ----------------
__global__ void convert_x_kernel(const float* __restrict__ x) {
    if (blockIdx.x == 0 && threadIdx.x < E_NUM) g_cnt[threadIdx.x] = 0;
    const size_t NX = (size_t)T_TOK * H_DIM / 4;
    size_t stride = (size_t)gridDim.x * blockDim.x;
    for (size_t i = (size_t)blockIdx.x * blockDim.x + threadIdx.x; i < NX; i += stride) {
        float4 v = ((const float4*)x)[i];
        __half2 h[2];
        h[0] = __floats2half2_rn(v.x, v.y);
        h[1] = __floats2half2_rn(v.z, v.w);
        *(uint2*)(g_xh + i * 4) = *(uint2*)h;
    }
}

// ---------------- router ----------------
__global__ void router_kernel(const float* __restrict__ x,
                              const float* __restrict__ gate_w,
                              float* __restrict__ logits_out) {
    const int TPB = 4;
    __shared__ float xs[TPB][H_DIM];
    __shared__ float lg[TPB][E_NUM];

    int t0 = blockIdx.x * TPB;
    const float4* xv  = (const float4*)(x + (size_t)t0 * H_DIM);
    float4*       xsv = (float4*)&xs[0][0];
    for (int i = threadIdx.x; i < TPB * H_DIM / 4; i += blockDim.x) xsv[i] = xv[i];
    __syncthreads();

    int warp = threadIdx.x >> 5;
    int lane = threadIdx.x & 31;

    for (int sub = 0; sub < 4; sub++) {
        int e = warp + sub * 8;
        const float* w = gate_w + (size_t)e * H_DIM;
        float p0 = 0.f, p1 = 0.f, p2 = 0.f, p3 = 0.f;
        for (int h = lane; h < H_DIM; h += 32) {
            float wv = w[h];
            p0 += xs[0][h] * wv;
            p1 += xs[1][h] * wv;
            p2 += xs[2][h] * wv;
            p3 += xs[3][h] * wv;
        }
        for (int o = 16; o; o >>= 1) {
            p0 += __shfl_xor_sync(0xFFFFFFFFu, p0, o);
            p1 += __shfl_xor_sync(0xFFFFFFFFu, p1, o);
            p2 += __shfl_xor_sync(0xFFFFFFFFu, p2, o);
            p3 += __shfl_xor_sync(0xFFFFFFFFu, p3, o);
        }
        if (lane == 0) { lg[0][e] = p0; lg[1][e] = p1; lg[2][e] = p2; lg[3][e] = p3; }
    }
    __syncthreads();

    if (warp < TPB) {
        int t = t0 + warp;
        float logit = lg[warp][lane];
        if (logits_out) logits_out[(size_t)t * E_NUM + lane] = logit;

        float m = logit;
        for (int o = 16; o; o >>= 1) m = fmaxf(m, __shfl_xor_sync(0xFFFFFFFFu, m, o));
        float ex = expf(logit - m);
        float s = ex;
        for (int o = 16; o; o >>= 1) s += __shfl_xor_sync(0xFFFFFFFFu, s, o);
        float prob = ex / s;

        float v = prob;
        float wsum = 0.f;
        float selw[K_TOP];
        int   sele[K_TOP];
#pragma unroll
        for (int k = 0; k < K_TOP; k++) {
            float mv = v;
            for (int o = 16; o; o >>= 1) mv = fmaxf(mv, __shfl_xor_sync(0xFFFFFFFFu, mv, o));
            unsigned msk = __ballot_sync(0xFFFFFFFFu, v == mv);
            int src = __ffs(msk) - 1;
            if (lane == 0) { sele[k] = src; selw[k] = mv; wsum += mv; }
            if (lane == src) v = -1.f;
        }
        if (lane == 0) {
#pragma unroll
            for (int k = 0; k < K_TOP; k++) {
                int e = sele[k];
                float wn = selw[k] / wsum;
                int pos = atomicAdd(&g_cnt[e], 1);
                g_list_tok[e * T_TOK + pos] = t;
                g_list_w[e * T_TOK + pos]   = wn;
                g_list_tk[e * T_TOK + pos]  = t * K_TOP + k;
            }
        }
    }
}

// ---------------- fused scan + remap ----------------
__global__ void scan_remap_kernel() {
    if (threadIdx.x == 0) {
        int acc = 0;
        for (int e = 0; e < E_NUM; e++) { g_off[e] = acc; acc += g_cnt[e]; }
        g_off[E_NUM] = acc;
    }
    __syncthreads();
    for (int e = 0; e < E_NUM; e++) {
        int n = g_cnt[e], o = g_off[e];
        for (int p = threadIdx.x; p < n; p += blockDim.x)
            g_slot_of[g_list_tk[e * T_TOK + p]] = o + p;
    }
}

__device__ __forceinline__ float silu_f(float g) { return g / (1.f + expf(-g)); }

__device__ __forceinline__ uint32_t smem_u32(const void* p) {
    uint32_t a;
    asm("{ .reg .u64 t; cvta.to.shared.u64 t, %1; cvt.u32.u64 %0, t; }" : "=r"(a) : "l"(p));
    return a;
}

#define LDM4(r0, r1, r2, r3, addr) \
    asm volatile("ldmatrix.sync.aligned.m8n8.x4.shared.b16 {%0,%1,%2,%3}, [%4];" \
                 : "=r"(r0), "=r"(r1), "=r"(r2), "=r"(r3) : "r"(addr))

#define CP16(dst, src) \
    asm volatile("cp.async.cg.shared.global [%0], [%1], 16;" :: "r"(dst), "l"(src) : "memory")
#define CP_COMMIT() asm volatile("cp.async.commit_group;" ::: "memory")
#define CP_WAIT(n)  asm volatile("cp.async.wait_group %0;" :: "n"(n) : "memory")

__device__ __forceinline__ void mma16(float* c, uint32_t a0, uint32_t a1, uint32_t a2, uint32_t a3,
                                      uint32_t b0, uint32_t b1) {
    asm volatile("mma.sync.aligned.m16n8k16.row.col.f32.f16.f16.f32 "
                 "{%0,%1,%2,%3}, {%4,%5,%6,%7}, {%8,%9}, {%0,%1,%2,%3};"
                 : "+f"(c[0]), "+f"(c[1]), "+f"(c[2]), "+f"(c[3])
                 : "r"(a0), "r"(a1), "r"(a2), "r"(a3), "r"(b0), "r"(b1));
}

// cvt 8 fp32 (2x float4) -> 16B fp16 STS.128
__device__ __forceinline__ void cvt_sts(unsigned char* dst, float4 v0, float4 v1) {
    __half2 h[4];
    h[0] = __floats2half2_rn(v0.x, v0.y);
    h[1] = __floats2half2_rn(v0.z, v0.w);
    h[2] = __floats2half2_rn(v1.x, v1.y);
    h[3] = __floats2half2_rn(v1.z, v1.w);
    *(uint4*)dst = *(uint4*)h;
}

extern __shared__ unsigned char dsm[];

// ---------------- grouped gate+up GEMM ----------------
// A: fp16 cp.async 4-stage. B: fp32 LDG -> reg cvt -> STS fp16, double-buffered dest.
__global__ __launch_bounds__(256, 2) void gateup_kernel(const float* __restrict__ gw,
                                                        const float* __restrict__ uw) {
    int e  = blockIdx.z;
    int n  = g_cnt[e];
    int m0 = blockIdx.x * BM;
    if (m0 >= n) return;
    int c0 = blockIdx.y * BN;

    uint32_t sbase = smem_u32(dsm);
    int tid  = threadIdx.x;
    int lane = tid & 31;
    int warp = tid >> 5;
    int wM = warp & 3;
    int wN = warp >> 2;

    // A loader (cp.async): 2 threads per row, 32 B per slab per thread
    int lr = tid >> 1;
    int hf = tid & 1;
    int tokA = g_list_tok[e * T_TOK + min(m0 + lr, n - 1)];
    const __half* pA = g_xh + (size_t)tokA * H_DIM + hf * 16;
    uint32_t soA = lr * RSB + hf * 32;

    // B loader (LDG fp32): chunk c = tid + 256j (j=0,1); row = c>>2 (0..127), 32B piece (c&3)
    const float* pB[2];
    uint32_t soBd[2];
#pragma unroll
    for (int j = 0; j < 2; j++) {
        int c = tid + 256 * j;
        int row = c >> 2;                  // <64 gate, >=64 up
        const float* base = (row < 64)
            ? gw + ((size_t)e * I_DIM + (c0 + row)) * H_DIM
            : uw + ((size_t)e * I_DIM + (c0 + row - 64)) * H_DIM;
        pB[j]   = base + (c & 3) * 8;
        soBd[j] = row * RSB + (c & 3) * 16;
    }

    int mat = lane >> 3, rr = lane & 7;
    uint32_t aBase[2], bgBase[2], buBase[2];
#pragma unroll
    for (int mi = 0; mi < 2; mi++)
        aBase[mi] = sbase + (uint32_t)((wM * 32 + mi * 16 + (mat & 1) * 8 + rr) * RSB + (mat >> 1) * 16);
#pragma unroll
    for (int p = 0; p < 2; p++) {
        uint32_t roff = (uint32_t)((wN * 32 + p * 16 + (mat >> 1) * 8 + rr) * RSB + (mat & 1) * 16);
        bgBase[p] = sbase + GU_DEST + roff;            // gate rows 0..63
        buBase[p] = sbase + GU_DEST + 64 * RSB + roff; // up rows 64..127
    }

    float cg[2][4][4] = {};
    float cu[2][4][4] = {};

#define GU_A_ISSUE(i)                                                     \
    { uint32_t bb = ((i) & (STAGES - 1)) * A_STG;                         \
      const __half* sa = pA + (i) * 32;                                   \
      CP16(sbase + bb + soA, sa); CP16(sbase + bb + soA + 16, sa + 8); }

    GU_A_ISSUE(0); CP_COMMIT();
    GU_A_ISSUE(1); CP_COMMIT();
    GU_A_ISSUE(2); CP_COMMIT();

    // B slab 0 -> dest buffer 0 (visible after first top-of-loop sync)
    {
        float4 v0a = *(const float4*)(pB[0]);
        float4 v0b = *(const float4*)(pB[0] + 4);
        float4 v1a = *(const float4*)(pB[1]);
        float4 v1b = *(const float4*)(pB[1] + 4);
        cvt_sts(dsm + GU_DEST + soBd[0], v0a, v0b);
        cvt_sts(dsm + GU_DEST + soBd[1], v1a, v1b);
    }

    for (int i = 0; i < GU_NC; i++) {
        CP_WAIT(STAGES - 2);
        __syncthreads();
        uint32_t ast = (i & (STAGES - 1)) * A_STG;
        uint32_t dst = (i & 1) * GU_DBUF;

        bool pre = (i + 1 < GU_NC);
        float4 nb0a, nb0b, nb1a, nb1b;
        if (pre) {
            const float* q0 = pB[0] + (i + 1) * 32;
            const float* q1 = pB[1] + (i + 1) * 32;
            nb0a = *(const float4*)(q0); nb0b = *(const float4*)(q0 + 4);
            nb1a = *(const float4*)(q1); nb1b = *(const float4*)(q1 + 4);
        }

#pragma unroll
        for (int ks = 0; ks < 2; ks++) {
            uint32_t af[2][4];
#pragma unroll
            for (int mi = 0; mi < 2; mi++)
                LDM4(af[mi][0], af[mi][1], af[mi][2], af[mi][3], aBase[mi] + ast + ks * 32);
            uint32_t gf[2][4], uf[2][4];
#pragma unroll
            for (int p = 0; p < 2; p++) {
                LDM4(gf[p][0], gf[p][1], gf[p][2], gf[p][3], bgBase[p] + dst + ks * 32);
                LDM4(uf[p][0], uf[p][1], uf[p][2], uf[p][3], buBase[p] + dst + ks * 32);
            }
#pragma unroll
            for (int t = 0; t < 4; t++) {
                int p = t >> 1, q = (t & 1) * 2;
#pragma unroll
                for (int mi = 0; mi < 2; mi++) {
                    mma16(cg[mi][t], af[mi][0], af[mi][1], af[mi][2], af[mi][3], gf[p][q], gf[p][q + 1]);
                    mma16(cu[mi][t], af[mi][0], af[mi][1], af[mi][2], af[mi][3], uf[p][q], uf[p][q + 1]);
                }
            }
        }

        if (pre) {
            uint32_t nd = GU_DEST + ((i + 1) & 1) * GU_DBUF;
            cvt_sts(dsm + nd + soBd[0], nb0a, nb0b);
            cvt_sts(dsm + nd + soBd[1], nb1a, nb1b);
        }
        if (i + STAGES - 1 < GU_NC) GU_A_ISSUE(i + STAGES - 1);
        CP_COMMIT();
    }
#undef GU_A_ISSUE

    // ---- epilogue ----
    int off = g_off[e];
    int g  = lane >> 2;
    int tq = lane & 3;
#pragma unroll
    for (int mi = 0; mi < 2; mi++) {
        int r0 = m0 + wM * 32 + mi * 16 + g;
        int r1 = r0 + 8;
        float w0 = (r0 < n) ? g_list_w[e * T_TOK + r0] : 0.f;
        float w1 = (r1 < n) ? g_list_w[e * T_TOK + r1] : 0.f;
#pragma unroll
        for (int t = 0; t < 4; t++) {
            int col = c0 + wN * 32 + t * 8 + 2 * tq;
            if (r0 < n) {
                float ox = silu_f(cg[mi][t][0]) * cu[mi][t][0] * w0;
                float oy = silu_f(cg[mi][t][1]) * cu[mi][t][1] * w0;
                *(__half2*)&g_act[((size_t)(off + r0)) * I_DIM + col] = __floats2half2_rn(ox, oy);
            }
            if (r1 < n) {
                float ox = silu_f(cg[mi][t][2]) * cu[mi][t][2] * w1;
                float oy = silu_f(cg[mi][t][3]) * cu[mi][t][3] * w1;
                *(__half2*)&g_act[((size_t)(off + r1)) * I_DIM + col] = __floats2half2_rn(ox, oy);
            }
        }
    }
}

// ---------------- grouped down GEMM (BN=128: 2x A-fragment reuse) ----------------
__global__ __launch_bounds__(256, 2) void down_kernel(const float* __restrict__ dw) {
    int e  = blockIdx.z;
    int n  = g_cnt[e];
    int m0 = blockIdx.x * BM;
    if (m0 >= n) return;
    int c0  = blockIdx.y * DN_BN;
    int off = g_off[e];

    uint32_t sbase = smem_u32(dsm);
    int tid  = threadIdx.x;
    int lane = tid & 31;
    int warp = tid >> 5;
    int wM = warp & 3;
    int wN = warp >> 2;     // 0..1, each covers 64 N columns

    int lr = tid >> 1;
    int hf = tid & 1;
    const __half* pA = g_act + (size_t)(off + min(m0 + lr, n - 1)) * I_DIM + hf * 16;
    uint32_t soA = lr * RSB + hf * 32;

    // B loader: chunk c = tid + 256j (j=0,1); row = c>>2 (0..127), 32B piece (c&3)
    const float* pB[2];
    uint32_t soBd[2];
#pragma unroll
    for (int j = 0; j < 2; j++) {
        int c = tid + 256 * j;
        int row = c >> 2;
        pB[j]   = dw + ((size_t)e * H_DIM + (c0 + row)) * I_DIM + (c & 3) * 8;
        soBd[j] = row * RSB + (c & 3) * 16;
    }

    int mat = lane >> 3, rr = lane & 7;
    uint32_t aBase[2], bBase[4];
#pragma unroll
    for (int mi = 0; mi < 2; mi++)
        aBase[mi] = sbase + (uint32_t)((wM * 32 + mi * 16 + (mat & 1) * 8 + rr) * RSB + (mat >> 1) * 16);
#pragma unroll
    for (int p = 0; p < 4; p++)
        bBase[p] = sbase + DN_DEST + (uint32_t)((wN * 64 + p * 16 + (mat >> 1) * 8 + rr) * RSB + (mat & 1) * 16);

    float c[2][8][4] = {};

#define DN_A_ISSUE(i)                                                     \
    { uint32_t bb = ((i) & (STAGES - 1)) * A_STG;                         \
      const __half* sa = pA + (i) * 32;                                   \
      CP16(sbase + bb + soA, sa); CP16(sbase + bb + soA + 16, sa + 8); }

    DN_A_ISSUE(0); CP_COMMIT();
    DN_A_ISSUE(1); CP_COMMIT();
    DN_A_ISSUE(2); CP_COMMIT();

    {
        float4 v0a = *(const float4*)(pB[0]);
        float4 v0b = *(const float4*)(pB[0] + 4);
        float4 v1a = *(const float4*)(pB[1]);
        float4 v1b = *(const float4*)(pB[1] + 4);
        cvt_sts(dsm + DN_DEST + soBd[0], v0a, v0b);
        cvt_sts(dsm + DN_DEST + soBd[1], v1a, v1b);
    }

    for (int i = 0; i < DN_NC; i++) {
        CP_WAIT(STAGES - 2);
        __syncthreads();
        uint32_t ast = (i & (STAGES - 1)) * A_STG;
        uint32_t dst = (i & 1) * DN_DBUF;

        bool pre = (i + 1 < DN_NC);
        float4 nb0a, nb0b, nb1a, nb1b;
        if (pre) {
            const float* q0 = pB[0] + (i + 1) * 32;
            const float* q1 = pB[1] + (i + 1) * 32;
            nb0a = *(const float4*)(q0); nb0b = *(const float4*)(q0 + 4);
            nb1a = *(const float4*)(q1); nb1b = *(const float4*)(q1 + 4);
        }

#pragma unroll
        for (int ks = 0; ks < 2; ks++) {
            uint32_t af[2][4];
#pragma unroll
            for (int mi = 0; mi < 2; mi++)
                LDM4(af[mi][0], af[mi][1], af[mi][2], af[mi][3], aBase[mi] + ast + ks * 32);
            uint32_t bf[4][4];
#pragma unroll
            for (int p = 0; p < 4; p++)
                LDM4(bf[p][0], bf[p][1], bf[p][2], bf[p][3], bBase[p] + dst + ks * 32);
#pragma unroll
            for (int t = 0; t < 8; t++) {
                int p = t >> 1, q = (t & 1) * 2;
#pragma unroll
                for (int mi = 0; mi < 2; mi++)
                    mma16(c[mi][t], af[mi][0], af[mi][1], af[mi][2], af[mi][3], bf[p][q], bf[p][q + 1]);
            }
        }

        if (pre) {
            uint32_t nd = DN_DEST + ((i + 1) & 1) * DN_DBUF;
            cvt_sts(dsm + nd + soBd[0], nb0a, nb0b);
            cvt_sts(dsm + nd + soBd[1], nb1a, nb1b);
        }
        if (i + STAGES - 1 < DN_NC) DN_A_ISSUE(i + STAGES - 1);
        CP_COMMIT();
    }
#undef DN_A_ISSUE

    int g  = lane >> 2;
    int tq = lane & 3;
#pragma unroll
    for (int mi = 0; mi < 2; mi++) {
        int r0 = m0 + wM * 32 + mi * 16 + g;
        int r1 = r0 + 8;
#pragma unroll
        for (int t = 0; t < 8; t++) {
            int col = c0 + wN * 64 + t * 8 + 2 * tq;
            if (r0 < n) {
                float2 o = make_float2(c[mi][t][0], c[mi][t][1]);
                *(float2*)&g_pair[((size_t)(off + r0)) * H_DIM + col] = o;
            }
            if (r1 < n) {
                float2 o = make_float2(c[mi][t][2], c[mi][t][3]);
                *(float2*)&g_pair[((size_t)(off + r1)) * H_DIM + col] = o;
            }
        }
    }
}

// ---------------- per-token reduction ----------------
__global__ void reduce_kernel(float* __restrict__ out) {
    int t = blockIdx.x;
    int s[K_TOP];
#pragma unroll
    for (int k = 0; k < K_TOP; k++) s[k] = g_slot_of[t * K_TOP + k];
    const float4* base = (const float4*)g_pair;
    float4* ob = (float4*)(out + (size_t)t * H_DIM);
    for (int i = threadIdx.x; i < H_DIM / 4; i += blockDim.x) {
        float4 acc = make_float4(0.f, 0.f, 0.f, 0.f);
#pragma unroll
        for (int k = 0; k < K_TOP; k++) {
            float4 v = base[(size_t)s[k] * (H_DIM / 4) + i];
            acc.x += v.x; acc.y += v.y; acc.z += v.z; acc.w += v.w;
        }
        ob[i] = acc;
    }
}

// ---------------- launch ----------------
extern "C" void kernel_launch(void* const* d_in, const int* in_sizes, int n_in,
                              void* d_out, int out_size) {
    const float* x      = (const float*)d_in[0];
    const float* gate_w = (const float*)d_in[1];
    const float* gw     = (const float*)d_in[2];
    const float* uw     = (const float*)d_in[3];
    const float* dw     = (const float*)d_in[4];
    float* out = (float*)d_out;

    float* logits = (out_size >= T_TOK * H_DIM + T_TOK * E_NUM) ? (out + (size_t)T_TOK * H_DIM)
                                                                : (float*)0;

    cudaFuncSetAttribute(gateup_kernel, cudaFuncAttributeMaxDynamicSharedMemorySize, GU_SMEM);
    cudaFuncSetAttribute(down_kernel,   cudaFuncAttributeMaxDynamicSharedMemorySize, DN_SMEM);

    convert_x_kernel<<<256, 256>>>(x);
    router_kernel<<<T_TOK / 4, 256>>>(x, gate_w, logits);
    scan_remap_kernel<<<1, 256>>>();
    gateup_kernel<<<dim3(T_TOK / BM, I_DIM / BN, E_NUM), 256, GU_SMEM>>>(gw, uw);
    down_kernel<<<dim3(T_TOK / BM, H_DIM / DN_BN, E_NUM), 256, DN_SMEM>>>(dw);
    reduce_kernel<<<T_TOK, 256>>>(out);
}

// round 14
// speedup vs baseline: 1.2125x; 1.0504x over previous
#include <cuda_runtime.h>
#include <cuda_fp16.h>
#include <math.h>
#include <stdint.h>

#define T_TOK 1024
#define H_DIM 2048
#define I_DIM 768
#define E_NUM 32
#define K_TOP 8

#define BM 128
#define BN 64            // gateup N tile (x2 for gate+up)
#define DN_BN 128        // down N tile
#define BK 32            // k-floats per slab
#define RSB 80           // fp16 smem row stride bytes (conflict-free ldmatrix)
#define ASTAGES 6        // A cp.async stages (3 pairs)

#define A_STG    (BM * RSB)                 // 10240
#define GU_SLABB (2 * BN * RSB)             // 10240 (gate rows 0..63, up 64..127)
#define GU_PBUF  (2 * GU_SLABB)             // 20480 (two slabs of a pair)
#define GU_DEST  (ASTAGES * A_STG)          // 61440
#define GU_SMEM  (GU_DEST + 2 * GU_PBUF)    // 102400 -> 2 CTAs/SM

#define DN_SLABB (DN_BN * RSB)              // 10240
#define DN_PBUF  (2 * DN_SLABB)             // 20480
#define DN_DEST  (ASTAGES * A_STG)
#define DN_SMEM  (DN_DEST + 2 * DN_PBUF)    // 102400 -> 2 CTAs/SM

#define GU_NC (H_DIM / BK)                  // 64 slabs
#define GU_NP (GU_NC / 2)                   // 32 pairs
#define DN_NC (I_DIM / BK)                  // 24 slabs
#define DN_NP (DN_NC / 2)                   // 12 pairs

// ---------------- scratch ----------------
__device__ int    g_cnt[E_NUM];
__device__ int    g_off[E_NUM + 1];
__device__ int    g_list_tok[E_NUM * T_TOK];
__device__ float  g_list_w[E_NUM * T_TOK];
__device__ int    g_list_tk[E_NUM * T_TOK];
__device__ int    g_slot_of[T_TOK * K_TOP];
__device__ __half g_act[(size_t)T_TOK * K_TOP * I_DIM];
__device__ __half g_pair[(size_t)T_TOK * K_TOP * H_DIM];   // fp16 now (33MB)
__device__ __half g_xh[(size_t)T_TOK * H_DIM];

__global__ void zero_cnt_kernel() {
    if (threadIdx.x < E_NUM) g_cnt[threadIdx.x] = 0;
}

// ---------------- router (+ writes fp16 copy of x) ----------------
__global__ void router_kernel(const float* __restrict__ x,
                              const float* __restrict__ gate_w,
                              float* __restrict__ logits_out) {
    const int TPB = 4;
    __shared__ float xs[TPB][H_DIM];
    __shared__ float lg[TPB][E_NUM];

    int t0 = blockIdx.x * TPB;
    const float4* xv  = (const float4*)(x + (size_t)t0 * H_DIM);
    float4*       xsv = (float4*)&xs[0][0];
    for (int i = threadIdx.x; i < TPB * H_DIM / 4; i += blockDim.x) xsv[i] = xv[i];
    __syncthreads();

    // fp16 copy of these 4 token rows
    {
        const float* xf = &xs[0][0];
        __half2* dst = (__half2*)(g_xh + (size_t)t0 * H_DIM);
        for (int i = threadIdx.x; i < TPB * H_DIM / 2; i += blockDim.x)
            dst[i] = __floats2half2_rn(xf[2 * i], xf[2 * i + 1]);
    }

    int warp = threadIdx.x >> 5;
    int lane = threadIdx.x & 31;

    for (int sub = 0; sub < 4; sub++) {
        int e = warp + sub * 8;
        const float* w = gate_w + (size_t)e * H_DIM;
        float p0 = 0.f, p1 = 0.f, p2 = 0.f, p3 = 0.f;
        for (int h = lane; h < H_DIM; h += 32) {
            float wv = w[h];
            p0 += xs[0][h] * wv;
            p1 += xs[1][h] * wv;
            p2 += xs[2][h] * wv;
            p3 += xs[3][h] * wv;
        }
        for (int o = 16; o; o >>= 1) {
            p0 += __shfl_xor_sync(0xFFFFFFFFu, p0, o);
            p1 += __shfl_xor_sync(0xFFFFFFFFu, p1, o);
            p2 += __shfl_xor_sync(0xFFFFFFFFu, p2, o);
            p3 += __shfl_xor_sync(0xFFFFFFFFu, p3, o);
        }
        if (lane == 0) { lg[0][e] = p0; lg[1][e] = p1; lg[2][e] = p2; lg[3][e] = p3; }
    }
    __syncthreads();

    if (warp < TPB) {
        int t = t0 + warp;
        float logit = lg[warp][lane];
        if (logits_out) logits_out[(size_t)t * E_NUM + lane] = logit;

        float m = logit;
        for (int o = 16; o; o >>= 1) m = fmaxf(m, __shfl_xor_sync(0xFFFFFFFFu, m, o));
        float ex = expf(logit - m);
        float s = ex;
        for (int o = 16; o; o >>= 1) s += __shfl_xor_sync(0xFFFFFFFFu, s, o);
        float prob = ex / s;

        float v = prob;
        float wsum = 0.f;
        float selw[K_TOP];
        int   sele[K_TOP];
#pragma unroll
        for (int k = 0; k < K_TOP; k++) {
            float mv = v;
            for (int o = 16; o; o >>= 1) mv = fmaxf(mv, __shfl_xor_sync(0xFFFFFFFFu, mv, o));
            unsigned msk = __ballot_sync(0xFFFFFFFFu, v == mv);
            int src = __ffs(msk) - 1;
            if (lane == 0) { sele[k] = src; selw[k] = mv; wsum += mv; }
            if (lane == src) v = -1.f;
        }
        if (lane == 0) {
#pragma unroll
            for (int k = 0; k < K_TOP; k++) {
                int e = sele[k];
                float wn = selw[k] / wsum;
                int pos = atomicAdd(&g_cnt[e], 1);
                g_list_tok[e * T_TOK + pos] = t;
                g_list_w[e * T_TOK + pos]   = wn;
                g_list_tk[e * T_TOK + pos]  = t * K_TOP + k;
            }
        }
    }
}

// ---------------- fused scan + remap ----------------
__global__ void scan_remap_kernel() {
    if (threadIdx.x == 0) {
        int acc = 0;
        for (int e = 0; e < E_NUM; e++) { g_off[e] = acc; acc += g_cnt[e]; }
        g_off[E_NUM] = acc;
    }
    __syncthreads();
    for (int e = 0; e < E_NUM; e++) {
        int n = g_cnt[e], o = g_off[e];
        for (int p = threadIdx.x; p < n; p += blockDim.x)
            g_slot_of[g_list_tk[e * T_TOK + p]] = o + p;
    }
}

__device__ __forceinline__ float silu_f(float g) { return g / (1.f + expf(-g)); }

__device__ __forceinline__ uint32_t smem_u32(const void* p) {
    uint32_t a;
    asm("{ .reg .u64 t; cvta.to.shared.u64 t, %1; cvt.u32.u64 %0, t; }" : "=r"(a) : "l"(p));
    return a;
}

#define LDM4(r0, r1, r2, r3, addr) \
    asm volatile("ldmatrix.sync.aligned.m8n8.x4.shared.b16 {%0,%1,%2,%3}, [%4];" \
                 : "=r"(r0), "=r"(r1), "=r"(r2), "=r"(r3) : "r"(addr))

#define CP16(dst, src) \
    asm volatile("cp.async.cg.shared.global [%0], [%1], 16;" :: "r"(dst), "l"(src) : "memory")
#define CP_COMMIT() asm volatile("cp.async.commit_group;" ::: "memory")
#define CP_WAIT(n)  asm volatile("cp.async.wait_group %0;" :: "n"(n) : "memory")

__device__ __forceinline__ void mma16(float* c, uint32_t a0, uint32_t a1, uint32_t a2, uint32_t a3,
                                      uint32_t b0, uint32_t b1) {
    asm volatile("mma.sync.aligned.m16n8k16.row.col.f32.f16.f16.f32 "
                 "{%0,%1,%2,%3}, {%4,%5,%6,%7}, {%8,%9}, {%0,%1,%2,%3};"
                 : "+f"(c[0]), "+f"(c[1]), "+f"(c[2]), "+f"(c[3])
                 : "r"(a0), "r"(a1), "r"(a2), "r"(a3), "r"(b0), "r"(b1));
}

// cvt 8 fp32 (2x float4) -> 16B fp16 STS.128
__device__ __forceinline__ void cvt_sts(unsigned char* dst, float4 v0, float4 v1) {
    __half2 h[4];
    h[0] = __floats2half2_rn(v0.x, v0.y);
    h[1] = __floats2half2_rn(v0.z, v0.w);
    h[2] = __floats2half2_rn(v1.x, v1.y);
    h[3] = __floats2half2_rn(v1.z, v1.w);
    *(uint4*)dst = *(uint4*)h;
}

extern __shared__ unsigned char dsm[];

// ---------------- grouped gate+up GEMM (pair loop: 2 K-slabs per barrier) ----------------
__global__ __launch_bounds__(256, 2) void gateup_kernel(const float* __restrict__ gw,
                                                        const float* __restrict__ uw) {
    int e  = blockIdx.z;
    int n  = g_cnt[e];
    int m0 = blockIdx.x * BM;
    if (m0 >= n) return;
    int c0 = blockIdx.y * BN;

    uint32_t sbase = smem_u32(dsm);
    int tid  = threadIdx.x;
    int lane = tid & 31;
    int warp = tid >> 5;
    int wM = warp & 3;
    int wN = warp >> 2;

    // A loader: 2 threads per row, 32 B per slab per thread
    int lr = tid >> 1;
    int hf = tid & 1;
    int tokA = g_list_tok[e * T_TOK + min(m0 + lr, n - 1)];
    const __half* pA = g_xh + (size_t)tokA * H_DIM + hf * 16;
    uint32_t soA = lr * RSB + hf * 32;

    // B loader (LDG fp32): chunk c = tid + 256j; row = c>>2 (0..127: <64 gate, >=64 up)
    const float* pB[2];
    uint32_t soBd[2];
#pragma unroll
    for (int j = 0; j < 2; j++) {
        int c = tid + 256 * j;
        int row = c >> 2;
        const float* base = (row < 64)
            ? gw + ((size_t)e * I_DIM + (c0 + row)) * H_DIM
            : uw + ((size_t)e * I_DIM + (c0 + row - 64)) * H_DIM;
        pB[j]   = base + (c & 3) * 8;
        soBd[j] = row * RSB + (c & 3) * 16;
    }

    int mat = lane >> 3, rr = lane & 7;
    uint32_t aBase[2], bgBase[2], buBase[2];     // bases WITHOUT stage/pair offsets
#pragma unroll
    for (int mi = 0; mi < 2; mi++)
        aBase[mi] = sbase + (uint32_t)((wM * 32 + mi * 16 + (mat & 1) * 8 + rr) * RSB + (mat >> 1) * 16);
#pragma unroll
    for (int p = 0; p < 2; p++) {
        uint32_t roff = (uint32_t)((wN * 32 + p * 16 + (mat >> 1) * 8 + rr) * RSB + (mat & 1) * 16);
        bgBase[p] = sbase + roff;
        buBase[p] = sbase + 64 * RSB + roff;
    }

    float cg[2][4][4] = {};
    float cu[2][4][4] = {};

    // issue A for pair p (slabs 2p, 2p+1)
#define GU_A_PAIR(pr)                                                         \
    { int s0_ = 2 * (pr), s1_ = s0_ + 1;                                      \
      uint32_t b0_ = (uint32_t)(s0_ % ASTAGES) * A_STG;                       \
      uint32_t b1_ = (uint32_t)(s1_ % ASTAGES) * A_STG;                       \
      const __half* a0_ = pA + s0_ * 32;                                      \
      const __half* a1_ = pA + s1_ * 32;                                      \
      CP16(sbase + b0_ + soA, a0_); CP16(sbase + b0_ + soA + 16, a0_ + 8);    \
      CP16(sbase + b1_ + soA, a1_); CP16(sbase + b1_ + soA + 16, a1_ + 8); }

#define GU_COMP(astOff, bOff)                                                 \
    { _Pragma("unroll")                                                       \
      for (int ks = 0; ks < 2; ks++) {                                        \
        uint32_t af[2][4];                                                    \
        _Pragma("unroll")                                                     \
        for (int mi = 0; mi < 2; mi++)                                        \
            LDM4(af[mi][0], af[mi][1], af[mi][2], af[mi][3], aBase[mi] + (astOff) + ks * 32); \
        uint32_t gf[2][4], uf[2][4];                                          \
        _Pragma("unroll")                                                     \
        for (int p = 0; p < 2; p++) {                                         \
            LDM4(gf[p][0], gf[p][1], gf[p][2], gf[p][3], bgBase[p] + (bOff) + ks * 32); \
            LDM4(uf[p][0], uf[p][1], uf[p][2], uf[p][3], buBase[p] + (bOff) + ks * 32); \
        }                                                                     \
        _Pragma("unroll")                                                     \
        for (int t = 0; t < 4; t++) {                                         \
            int p = t >> 1, q = (t & 1) * 2;                                  \
            _Pragma("unroll")                                                 \
            for (int mi = 0; mi < 2; mi++) {                                  \
                mma16(cg[mi][t], af[mi][0], af[mi][1], af[mi][2], af[mi][3], gf[p][q], gf[p][q + 1]); \
                mma16(cu[mi][t], af[mi][0], af[mi][1], af[mi][2], af[mi][3], uf[p][q], uf[p][q + 1]); \
            }                                                                 \
        }                                                                     \
      } }

    // prologue: A pairs 0,1; B pair 0 direct
    GU_A_PAIR(0); CP_COMMIT();
    GU_A_PAIR(1); CP_COMMIT();
    {
        float4 a0 = *(const float4*)(pB[0]);
        float4 a1 = *(const float4*)(pB[0] + 4);
        float4 b0 = *(const float4*)(pB[1]);
        float4 b1 = *(const float4*)(pB[1] + 4);
        cvt_sts(dsm + GU_DEST + soBd[0], a0, a1);
        cvt_sts(dsm + GU_DEST + soBd[1], b0, b1);
        const float* q0 = pB[0] + 32;
        const float* q1 = pB[1] + 32;
        a0 = *(const float4*)(q0); a1 = *(const float4*)(q0 + 4);
        b0 = *(const float4*)(q1); b1 = *(const float4*)(q1 + 4);
        cvt_sts(dsm + GU_DEST + GU_SLABB + soBd[0], a0, a1);
        cvt_sts(dsm + GU_DEST + GU_SLABB + soBd[1], b0, b1);
    }

    for (int j = 0; j < GU_NP; j++) {
        CP_WAIT(1);
        __syncthreads();
        uint32_t pbr = GU_DEST + (uint32_t)(j & 1) * GU_PBUF;
        uint32_t pbw = GU_DEST + (uint32_t)((j + 1) & 1) * GU_PBUF;
        int s0 = 2 * j;
        int sn0 = s0 + 2, sn1 = s0 + 3;
        bool hn = (j + 1 < GU_NP);

        // prefetch B slab sn0
        float4 na, nb, nc, nd;
        if (hn) {
            const float* q0 = pB[0] + sn0 * 32;
            const float* q1 = pB[1] + sn0 * 32;
            na = *(const float4*)(q0); nb = *(const float4*)(q0 + 4);
            nc = *(const float4*)(q1); nd = *(const float4*)(q1 + 4);
        }

        GU_COMP((uint32_t)(s0 % ASTAGES) * A_STG, pbr);

        if (hn) {
            cvt_sts(dsm + pbw + soBd[0], na, nb);
            cvt_sts(dsm + pbw + soBd[1], nc, nd);
            const float* q0 = pB[0] + sn1 * 32;
            const float* q1 = pB[1] + sn1 * 32;
            na = *(const float4*)(q0); nb = *(const float4*)(q0 + 4);
            nc = *(const float4*)(q1); nd = *(const float4*)(q1 + 4);
        }

        GU_COMP((uint32_t)((s0 + 1) % ASTAGES) * A_STG, pbr + GU_SLABB);

        if (hn) {
            cvt_sts(dsm + pbw + GU_SLABB + soBd[0], na, nb);
            cvt_sts(dsm + pbw + GU_SLABB + soBd[1], nc, nd);
        }
        if (j + 2 < GU_NP) GU_A_PAIR(j + 2);
        CP_COMMIT();
    }
#undef GU_A_PAIR
#undef GU_COMP

    // ---- epilogue ----
    int off = g_off[e];
    int g  = lane >> 2;
    int tq = lane & 3;
#pragma unroll
    for (int mi = 0; mi < 2; mi++) {
        int r0 = m0 + wM * 32 + mi * 16 + g;
        int r1 = r0 + 8;
        float w0 = (r0 < n) ? g_list_w[e * T_TOK + r0] : 0.f;
        float w1 = (r1 < n) ? g_list_w[e * T_TOK + r1] : 0.f;
#pragma unroll
        for (int t = 0; t < 4; t++) {
            int col = c0 + wN * 32 + t * 8 + 2 * tq;
            if (r0 < n) {
                float ox = silu_f(cg[mi][t][0]) * cu[mi][t][0] * w0;
                float oy = silu_f(cg[mi][t][1]) * cu[mi][t][1] * w0;
                *(__half2*)&g_act[((size_t)(off + r0)) * I_DIM + col] = __floats2half2_rn(ox, oy);
            }
            if (r1 < n) {
                float ox = silu_f(cg[mi][t][2]) * cu[mi][t][2] * w1;
                float oy = silu_f(cg[mi][t][3]) * cu[mi][t][3] * w1;
                *(__half2*)&g_act[((size_t)(off + r1)) * I_DIM + col] = __floats2half2_rn(ox, oy);
            }
        }
    }
}

// ---------------- grouped down GEMM (BN=128, pair loop) ----------------
__global__ __launch_bounds__(256, 2) void down_kernel(const float* __restrict__ dw) {
    int e  = blockIdx.z;
    int n  = g_cnt[e];
    int m0 = blockIdx.x * BM;
    if (m0 >= n) return;
    int c0  = blockIdx.y * DN_BN;
    int off = g_off[e];

    uint32_t sbase = smem_u32(dsm);
    int tid  = threadIdx.x;
    int lane = tid & 31;
    int warp = tid >> 5;
    int wM = warp & 3;
    int wN = warp >> 2;     // 0..1, each 64 N cols

    int lr = tid >> 1;
    int hf = tid & 1;
    const __half* pA = g_act + (size_t)(off + min(m0 + lr, n - 1)) * I_DIM + hf * 16;
    uint32_t soA = lr * RSB + hf * 32;

    const float* pB[2];
    uint32_t soBd[2];
#pragma unroll
    for (int j = 0; j < 2; j++) {
        int c = tid + 256 * j;
        int row = c >> 2;
        pB[j]   = dw + ((size_t)e * H_DIM + (c0 + row)) * I_DIM + (c & 3) * 8;
        soBd[j] = row * RSB + (c & 3) * 16;
    }

    int mat = lane >> 3, rr = lane & 7;
    uint32_t aBase[2], bBase[4];
#pragma unroll
    for (int mi = 0; mi < 2; mi++)
        aBase[mi] = sbase + (uint32_t)((wM * 32 + mi * 16 + (mat & 1) * 8 + rr) * RSB + (mat >> 1) * 16);
#pragma unroll
    for (int p = 0; p < 4; p++)
        bBase[p] = sbase + (uint32_t)((wN * 64 + p * 16 + (mat >> 1) * 8 + rr) * RSB + (mat & 1) * 16);

    float c[2][8][4] = {};

#define DN_A_PAIR(pr)                                                         \
    { int s0_ = 2 * (pr), s1_ = s0_ + 1;                                      \
      uint32_t b0_ = (uint32_t)(s0_ % ASTAGES) * A_STG;                       \
      uint32_t b1_ = (uint32_t)(s1_ % ASTAGES) * A_STG;                       \
      const __half* a0_ = pA + s0_ * 32;                                      \
      const __half* a1_ = pA + s1_ * 32;                                      \
      CP16(sbase + b0_ + soA, a0_); CP16(sbase + b0_ + soA + 16, a0_ + 8);    \
      CP16(sbase + b1_ + soA, a1_); CP16(sbase + b1_ + soA + 16, a1_ + 8); }

#define DN_COMP(astOff, bOff)                                                 \
    { _Pragma("unroll")                                                       \
      for (int ks = 0; ks < 2; ks++) {                                        \
        uint32_t af[2][4];                                                    \
        _Pragma("unroll")                                                     \
        for (int mi = 0; mi < 2; mi++)                                        \
            LDM4(af[mi][0], af[mi][1], af[mi][2], af[mi][3], aBase[mi] + (astOff) + ks * 32); \
        uint32_t bf[4][4];                                                    \
        _Pragma("unroll")                                                     \
        for (int p = 0; p < 4; p++)                                           \
            LDM4(bf[p][0], bf[p][1], bf[p][2], bf[p][3], bBase[p] + (bOff) + ks * 32); \
        _Pragma("unroll")                                                     \
        for (int t = 0; t < 8; t++) {                                         \
            int p = t >> 1, q = (t & 1) * 2;                                  \
            _Pragma("unroll")                                                 \
            for (int mi = 0; mi < 2; mi++)                                    \
                mma16(c[mi][t], af[mi][0], af[mi][1], af[mi][2], af[mi][3], bf[p][q], bf[p][q + 1]); \
        }                                                                     \
      } }

    DN_A_PAIR(0); CP_COMMIT();
    DN_A_PAIR(1); CP_COMMIT();
    {
        float4 a0 = *(const float4*)(pB[0]);
        float4 a1 = *(const float4*)(pB[0] + 4);
        float4 b0 = *(const float4*)(pB[1]);
        float4 b1 = *(const float4*)(pB[1] + 4);
        cvt_sts(dsm + DN_DEST + soBd[0], a0, a1);
        cvt_sts(dsm + DN_DEST + soBd[1], b0, b1);
        const float* q0 = pB[0] + 32;
        const float* q1 = pB[1] + 32;
        a0 = *(const float4*)(q0); a1 = *(const float4*)(q0 + 4);
        b0 = *(const float4*)(q1); b1 = *(const float4*)(q1 + 4);
        cvt_sts(dsm + DN_DEST + DN_SLABB + soBd[0], a0, a1);
        cvt_sts(dsm + DN_DEST + DN_SLABB + soBd[1], b0, b1);
    }

    for (int j = 0; j < DN_NP; j++) {
        CP_WAIT(1);
        __syncthreads();
        uint32_t pbr = DN_DEST + (uint32_t)(j & 1) * DN_PBUF;
        uint32_t pbw = DN_DEST + (uint32_t)((j + 1) & 1) * DN_PBUF;
        int s0 = 2 * j;
        int sn0 = s0 + 2, sn1 = s0 + 3;
        bool hn = (j + 1 < DN_NP);

        float4 na, nb, nc2, nd;
        if (hn) {
            const float* q0 = pB[0] + sn0 * 32;
            const float* q1 = pB[1] + sn0 * 32;
            na = *(const float4*)(q0); nb = *(const float4*)(q0 + 4);
            nc2 = *(const float4*)(q1); nd = *(const float4*)(q1 + 4);
        }

        DN_COMP((uint32_t)(s0 % ASTAGES) * A_STG, pbr);

        if (hn) {
            cvt_sts(dsm + pbw + soBd[0], na, nb);
            cvt_sts(dsm + pbw + soBd[1], nc2, nd);
            const float* q0 = pB[0] + sn1 * 32;
            const float* q1 = pB[1] + sn1 * 32;
            na = *(const float4*)(q0); nb = *(const float4*)(q0 + 4);
            nc2 = *(const float4*)(q1); nd = *(const float4*)(q1 + 4);
        }

        DN_COMP((uint32_t)((s0 + 1) % ASTAGES) * A_STG, pbr + DN_SLABB);

        if (hn) {
            cvt_sts(dsm + pbw + DN_SLABB + soBd[0], na, nb);
            cvt_sts(dsm + pbw + DN_SLABB + soBd[1], nc2, nd);
        }
        if (j + 2 < DN_NP) DN_A_PAIR(j + 2);
        CP_COMMIT();
    }
#undef DN_A_PAIR
#undef DN_COMP

    int g  = lane >> 2;
    int tq = lane & 3;
#pragma unroll
    for (int mi = 0; mi < 2; mi++) {
        int r0 = m0 + wM * 32 + mi * 16 + g;
        int r1 = r0 + 8;
#pragma unroll
        for (int t = 0; t < 8; t++) {
            int col = c0 + wN * 64 + t * 8 + 2 * tq;
            if (r0 < n)
                *(__half2*)&g_pair[((size_t)(off + r0)) * H_DIM + col] =
                    __floats2half2_rn(c[mi][t][0], c[mi][t][1]);
            if (r1 < n)
                *(__half2*)&g_pair[((size_t)(off + r1)) * H_DIM + col] =
                    __floats2half2_rn(c[mi][t][2], c[mi][t][3]);
        }
    }
}

// ---------------- per-token reduction (fp16 pairs -> fp32 out) ----------------
__global__ void reduce_kernel(float* __restrict__ out) {
    int t = blockIdx.x;
    int s[K_TOP];
#pragma unroll
    for (int k = 0; k < K_TOP; k++) s[k] = g_slot_of[t * K_TOP + k];
    int i = threadIdx.x;            // 256 threads, 8 halfs each
    float acc[8] = {};
#pragma unroll
    for (int k = 0; k < K_TOP; k++) {
        uint4 v = *(const uint4*)&g_pair[(size_t)s[k] * H_DIM + i * 8];
        const __half2* h = (const __half2*)&v;
#pragma unroll
        for (int q = 0; q < 4; q++) {
            float2 f = __half22float2(h[q]);
            acc[2 * q]     += f.x;
            acc[2 * q + 1] += f.y;
        }
    }
    float4* ob = (float4*)(out + (size_t)t * H_DIM + i * 8);
    ob[0] = make_float4(acc[0], acc[1], acc[2], acc[3]);
    ob[1] = make_float4(acc[4], acc[5], acc[6], acc[7]);
}

// ---------------- launch ----------------
extern "C" void kernel_launch(void* const* d_in, const int* in_sizes, int n_in,
                              void* d_out, int out_size) {
    const float* x      = (const float*)d_in[0];
    const float* gate_w = (const float*)d_in[1];
    const float* gw     = (const float*)d_in[2];
    const float* uw     = (const float*)d_in[3];
    const float* dw     = (const float*)d_in[4];
    float* out = (float*)d_out;

    float* logits = (out_size >= T_TOK * H_DIM + T_TOK * E_NUM) ? (out + (size_t)T_TOK * H_DIM)
                                                                : (float*)0;

    cudaFuncSetAttribute(gateup_kernel, cudaFuncAttributeMaxDynamicSharedMemorySize, GU_SMEM);
    cudaFuncSetAttribute(down_kernel,   cudaFuncAttributeMaxDynamicSharedMemorySize, DN_SMEM);

    zero_cnt_kernel<<<1, 32>>>();
    router_kernel<<<T_TOK / 4, 256>>>(x, gate_w, logits);
    scan_remap_kernel<<<1, 256>>>();
    gateup_kernel<<<dim3(T_TOK / BM, I_DIM / BN, E_NUM), 256, GU_SMEM>>>(gw, uw);
    down_kernel<<<dim3(T_TOK / BM, H_DIM / DN_BN, E_NUM), 256, DN_SMEM>>>(dw);
    reduce_kernel<<<T_TOK, 256>>>(out);
}

// round 15
// speedup vs baseline: 1.2428x; 1.0250x over previous
#include <cuda_runtime.h>
#include <cuda_fp16.h>
#include <math.h>
#include <stdint.h>

#define T_TOK 1024
#define H_DIM 2048
#define I_DIM 768
#define E_NUM 32
#define K_TOP 8

#define BM 128
#define BN 64            // gateup N tile (x2 for gate+up)
#define DN_BN 128        // down N tile
#define BK 32
#define RSB 80
#define ASTAGES 6

#define A_STG    (BM * RSB)                 // 10240
#define GU_SLABB (2 * BN * RSB)             // 10240
#define GU_PBUF  (2 * GU_SLABB)             // 20480
#define GU_DEST  (ASTAGES * A_STG)          // 61440
#define GU_SMEM  (GU_DEST + 2 * GU_PBUF)    // 102400

#define DN_SLABB (DN_BN * RSB)
#define DN_PBUF  (2 * DN_SLABB)
#define DN_DEST  (ASTAGES * A_STG)
#define DN_SMEM  (DN_DEST + 2 * DN_PBUF)    // 102400

#define MOE_SMEM 102400

#define GU_NC (H_DIM / BK)
#define GU_NP (GU_NC / 2)                   // 32
#define DN_NC (I_DIM / BK)
#define DN_NP (DN_NC / 2)                   // 12

#define GU_XT (T_TOK / BM)                  // 8
#define GU_YT (I_DIM / BN)                  // 12
#define DN_YT (H_DIM / DN_BN)               // 16
#define GU_PER_E (GU_XT * GU_YT)            // 96
#define DN_PER_E (GU_XT * DN_YT)            // 128
#define GU_ITEMS (GU_PER_E * E_NUM)         // 3072
#define TOT_ITEMS (GU_ITEMS + DN_PER_E * E_NUM)  // 7168

// ---------------- scratch ----------------
__device__ int    g_cnt[E_NUM];
__device__ int    g_off[E_NUM + 1];
__device__ int    g_list_tok[E_NUM * T_TOK];
__device__ float  g_list_w[E_NUM * T_TOK];
__device__ int    g_list_tk[E_NUM * T_TOK];
__device__ int    g_slot_of[T_TOK * K_TOP];
__device__ __half g_act[(size_t)T_TOK * K_TOP * I_DIM];
__device__ __half g_pair[(size_t)T_TOK * K_TOP * H_DIM];
__device__ __half g_xh[(size_t)T_TOK * H_DIM];
__device__ int    g_work;
__device__ int    g_done[E_NUM];

__global__ void zero_cnt_kernel() {
    if (threadIdx.x < E_NUM) { g_cnt[threadIdx.x] = 0; g_done[threadIdx.x] = 0; }
    if (threadIdx.x == 0) g_work = 0;
}

// ---------------- router (+ fp16 copy of x) ----------------
__global__ void router_kernel(const float* __restrict__ x,
                              const float* __restrict__ gate_w,
                              float* __restrict__ logits_out) {
    const int TPB = 4;
    __shared__ float xs[TPB][H_DIM];
    __shared__ float lg[TPB][E_NUM];

    int t0 = blockIdx.x * TPB;
    const float4* xv  = (const float4*)(x + (size_t)t0 * H_DIM);
    float4*       xsv = (float4*)&xs[0][0];
    for (int i = threadIdx.x; i < TPB * H_DIM / 4; i += blockDim.x) xsv[i] = xv[i];
    __syncthreads();

    {
        const float* xf = &xs[0][0];
        __half2* dst = (__half2*)(g_xh + (size_t)t0 * H_DIM);
        for (int i = threadIdx.x; i < TPB * H_DIM / 2; i += blockDim.x)
            dst[i] = __floats2half2_rn(xf[2 * i], xf[2 * i + 1]);
    }

    int warp = threadIdx.x >> 5;
    int lane = threadIdx.x & 31;

    for (int sub = 0; sub < 4; sub++) {
        int e = warp + sub * 8;
        const float* w = gate_w + (size_t)e * H_DIM;
        float p0 = 0.f, p1 = 0.f, p2 = 0.f, p3 = 0.f;
        for (int h = lane; h < H_DIM; h += 32) {
            float wv = w[h];
            p0 += xs[0][h] * wv;
            p1 += xs[1][h] * wv;
            p2 += xs[2][h] * wv;
            p3 += xs[3][h] * wv;
        }
        for (int o = 16; o; o >>= 1) {
            p0 += __shfl_xor_sync(0xFFFFFFFFu, p0, o);
            p1 += __shfl_xor_sync(0xFFFFFFFFu, p1, o);
            p2 += __shfl_xor_sync(0xFFFFFFFFu, p2, o);
            p3 += __shfl_xor_sync(0xFFFFFFFFu, p3, o);
        }
        if (lane == 0) { lg[0][e] = p0; lg[1][e] = p1; lg[2][e] = p2; lg[3][e] = p3; }
    }
    __syncthreads();

    if (warp < TPB) {
        int t = t0 + warp;
        float logit = lg[warp][lane];
        if (logits_out) logits_out[(size_t)t * E_NUM + lane] = logit;

        float m = logit;
        for (int o = 16; o; o >>= 1) m = fmaxf(m, __shfl_xor_sync(0xFFFFFFFFu, m, o));
        float ex = expf(logit - m);
        float s = ex;
        for (int o = 16; o; o >>= 1) s += __shfl_xor_sync(0xFFFFFFFFu, s, o);
        float prob = ex / s;

        float v = prob;
        float wsum = 0.f;
        float selw[K_TOP];
        int   sele[K_TOP];
#pragma unroll
        for (int k = 0; k < K_TOP; k++) {
            float mv = v;
            for (int o = 16; o; o >>= 1) mv = fmaxf(mv, __shfl_xor_sync(0xFFFFFFFFu, mv, o));
            unsigned msk = __ballot_sync(0xFFFFFFFFu, v == mv);
            int src = __ffs(msk) - 1;
            if (lane == 0) { sele[k] = src; selw[k] = mv; wsum += mv; }
            if (lane == src) v = -1.f;
        }
        if (lane == 0) {
#pragma unroll
            for (int k = 0; k < K_TOP; k++) {
                int e = sele[k];
                float wn = selw[k] / wsum;
                int pos = atomicAdd(&g_cnt[e], 1);
                g_list_tok[e * T_TOK + pos] = t;
                g_list_w[e * T_TOK + pos]   = wn;
                g_list_tk[e * T_TOK + pos]  = t * K_TOP + k;
            }
        }
    }
}

// ---------------- fused scan + remap ----------------
__global__ void scan_remap_kernel() {
    if (threadIdx.x == 0) {
        int acc = 0;
        for (int e = 0; e < E_NUM; e++) { g_off[e] = acc; acc += g_cnt[e]; }
        g_off[E_NUM] = acc;
    }
    __syncthreads();
    for (int e = 0; e < E_NUM; e++) {
        int n = g_cnt[e], o = g_off[e];
        for (int p = threadIdx.x; p < n; p += blockDim.x)
            g_slot_of[g_list_tk[e * T_TOK + p]] = o + p;
    }
}

__device__ __forceinline__ float silu_f(float g) { return g / (1.f + expf(-g)); }

__device__ __forceinline__ uint32_t smem_u32(const void* p) {
    uint32_t a;
    asm("{ .reg .u64 t; cvta.to.shared.u64 t, %1; cvt.u32.u64 %0, t; }" : "=r"(a) : "l"(p));
    return a;
}

#define LDM4(r0, r1, r2, r3, addr) \
    asm volatile("ldmatrix.sync.aligned.m8n8.x4.shared.b16 {%0,%1,%2,%3}, [%4];" \
                 : "=r"(r0), "=r"(r1), "=r"(r2), "=r"(r3) : "r"(addr))

#define CP16(dst, src) \
    asm volatile("cp.async.cg.shared.global [%0], [%1], 16;" :: "r"(dst), "l"(src) : "memory")
#define CP_COMMIT() asm volatile("cp.async.commit_group;" ::: "memory")
#define CP_WAIT(n)  asm volatile("cp.async.wait_group %0;" :: "n"(n) : "memory")

__device__ __forceinline__ void mma16(float* c, uint32_t a0, uint32_t a1, uint32_t a2, uint32_t a3,
                                      uint32_t b0, uint32_t b1) {
    asm volatile("mma.sync.aligned.m16n8k16.row.col.f32.f16.f16.f32 "
                 "{%0,%1,%2,%3}, {%4,%5,%6,%7}, {%8,%9}, {%0,%1,%2,%3};"
                 : "+f"(c[0]), "+f"(c[1]), "+f"(c[2]), "+f"(c[3])
                 : "r"(a0), "r"(a1), "r"(a2), "r"(a3), "r"(b0), "r"(b1));
}

__device__ __forceinline__ void cvt_sts(unsigned char* dst, float4 v0, float4 v1) {
    __half2 h[4];
    h[0] = __floats2half2_rn(v0.x, v0.y);
    h[1] = __floats2half2_rn(v0.z, v0.w);
    h[2] = __floats2half2_rn(v1.x, v1.y);
    h[3] = __floats2half2_rn(v1.z, v1.w);
    *(uint4*)dst = *(uint4*)h;
}

extern __shared__ unsigned char dsm[];

// ---------------- gateup tile ----------------
__device__ void do_gateup(int e, int m0, int c0,
                          const float* __restrict__ gw, const float* __restrict__ uw) {
    int n = g_cnt[e];
    int tid = threadIdx.x;
    if (m0 >= n) {
        __syncthreads();
        if (tid == 0) atomicAdd(&g_done[e], 1);
        return;
    }

    uint32_t sbase = smem_u32(dsm);
    int lane = tid & 31;
    int warp = tid >> 5;
    int wM = warp & 3;
    int wN = warp >> 2;

    int lr = tid >> 1;
    int hf = tid & 1;
    int tokA = g_list_tok[e * T_TOK + min(m0 + lr, n - 1)];
    const __half* pA = g_xh + (size_t)tokA * H_DIM + hf * 16;
    uint32_t soA = lr * RSB + hf * 32;

    const float* pB[2];
    uint32_t soBd[2];
#pragma unroll
    for (int j = 0; j < 2; j++) {
        int c = tid + 256 * j;
        int row = c >> 2;
        const float* base = (row < 64)
            ? gw + ((size_t)e * I_DIM + (c0 + row)) * H_DIM
            : uw + ((size_t)e * I_DIM + (c0 + row - 64)) * H_DIM;
        pB[j]   = base + (c & 3) * 8;
        soBd[j] = row * RSB + (c & 3) * 16;
    }

    int mat = lane >> 3, rr = lane & 7;
    uint32_t aBase[2], bgBase[2], buBase[2];
#pragma unroll
    for (int mi = 0; mi < 2; mi++)
        aBase[mi] = sbase + (uint32_t)((wM * 32 + mi * 16 + (mat & 1) * 8 + rr) * RSB + (mat >> 1) * 16);
#pragma unroll
    for (int p = 0; p < 2; p++) {
        uint32_t roff = (uint32_t)((wN * 32 + p * 16 + (mat >> 1) * 8 + rr) * RSB + (mat & 1) * 16);
        bgBase[p] = sbase + roff;
        buBase[p] = sbase + 64 * RSB + roff;
    }

    float cg[2][4][4] = {};
    float cu[2][4][4] = {};

#define GU_A_PAIR(pr)                                                         \
    { int s0_ = 2 * (pr), s1_ = s0_ + 1;                                      \
      uint32_t b0_ = (uint32_t)(s0_ % ASTAGES) * A_STG;                       \
      uint32_t b1_ = (uint32_t)(s1_ % ASTAGES) * A_STG;                       \
      const __half* a0_ = pA + s0_ * 32;                                      \
      const __half* a1_ = pA + s1_ * 32;                                      \
      CP16(sbase + b0_ + soA, a0_); CP16(sbase + b0_ + soA + 16, a0_ + 8);    \
      CP16(sbase + b1_ + soA, a1_); CP16(sbase + b1_ + soA + 16, a1_ + 8); }

#define GU_COMP(astOff, bOff)                                                 \
    { _Pragma("unroll")                                                       \
      for (int ks = 0; ks < 2; ks++) {                                        \
        uint32_t af[2][4];                                                    \
        _Pragma("unroll")                                                     \
        for (int mi = 0; mi < 2; mi++)                                        \
            LDM4(af[mi][0], af[mi][1], af[mi][2], af[mi][3], aBase[mi] + (astOff) + ks * 32); \
        uint32_t gf[2][4], uf[2][4];                                          \
        _Pragma("unroll")                                                     \
        for (int p = 0; p < 2; p++) {                                         \
            LDM4(gf[p][0], gf[p][1], gf[p][2], gf[p][3], bgBase[p] + (bOff) + ks * 32); \
            LDM4(uf[p][0], uf[p][1], uf[p][2], uf[p][3], buBase[p] + (bOff) + ks * 32); \
        }                                                                     \
        _Pragma("unroll")                                                     \
        for (int t = 0; t < 4; t++) {                                         \
            int p = t >> 1, q = (t & 1) * 2;                                  \
            _Pragma("unroll")                                                 \
            for (int mi = 0; mi < 2; mi++) {                                  \
                mma16(cg[mi][t], af[mi][0], af[mi][1], af[mi][2], af[mi][3], gf[p][q], gf[p][q + 1]); \
                mma16(cu[mi][t], af[mi][0], af[mi][1], af[mi][2], af[mi][3], uf[p][q], uf[p][q + 1]); \
            }                                                                 \
        }                                                                     \
      } }

    GU_A_PAIR(0); CP_COMMIT();
    GU_A_PAIR(1); CP_COMMIT();
    {
        float4 a0 = *(const float4*)(pB[0]);
        float4 a1 = *(const float4*)(pB[0] + 4);
        float4 b0 = *(const float4*)(pB[1]);
        float4 b1 = *(const float4*)(pB[1] + 4);
        cvt_sts(dsm + GU_DEST + soBd[0], a0, a1);
        cvt_sts(dsm + GU_DEST + soBd[1], b0, b1);
        const float* q0 = pB[0] + 32;
        const float* q1 = pB[1] + 32;
        a0 = *(const float4*)(q0); a1 = *(const float4*)(q0 + 4);
        b0 = *(const float4*)(q1); b1 = *(const float4*)(q1 + 4);
        cvt_sts(dsm + GU_DEST + GU_SLABB + soBd[0], a0, a1);
        cvt_sts(dsm + GU_DEST + GU_SLABB + soBd[1], b0, b1);
    }

    for (int j = 0; j < GU_NP; j++) {
        CP_WAIT(1);
        __syncthreads();
        uint32_t pbr = GU_DEST + (uint32_t)(j & 1) * GU_PBUF;
        uint32_t pbw = GU_DEST + (uint32_t)((j + 1) & 1) * GU_PBUF;
        int s0 = 2 * j;
        int sn0 = s0 + 2, sn1 = s0 + 3;
        bool hn = (j + 1 < GU_NP);

        float4 na, nb, nc, nd;
        if (hn) {
            const float* q0 = pB[0] + sn0 * 32;
            const float* q1 = pB[1] + sn0 * 32;
            na = *(const float4*)(q0); nb = *(const float4*)(q0 + 4);
            nc = *(const float4*)(q1); nd = *(const float4*)(q1 + 4);
        }

        GU_COMP((uint32_t)(s0 % ASTAGES) * A_STG, pbr);

        if (hn) {
            cvt_sts(dsm + pbw + soBd[0], na, nb);
            cvt_sts(dsm + pbw + soBd[1], nc, nd);
            const float* q0 = pB[0] + sn1 * 32;
            const float* q1 = pB[1] + sn1 * 32;
            na = *(const float4*)(q0); nb = *(const float4*)(q0 + 4);
            nc = *(const float4*)(q1); nd = *(const float4*)(q1 + 4);
        }

        GU_COMP((uint32_t)((s0 + 1) % ASTAGES) * A_STG, pbr + GU_SLABB);

        if (hn) {
            cvt_sts(dsm + pbw + GU_SLABB + soBd[0], na, nb);
            cvt_sts(dsm + pbw + GU_SLABB + soBd[1], nc, nd);
        }
        if (j + 2 < GU_NP) GU_A_PAIR(j + 2);
        CP_COMMIT();
    }
#undef GU_A_PAIR
#undef GU_COMP

    int off = g_off[e];
    int g  = lane >> 2;
    int tq = lane & 3;
#pragma unroll
    for (int mi = 0; mi < 2; mi++) {
        int r0 = m0 + wM * 32 + mi * 16 + g;
        int r1 = r0 + 8;
        float w0 = (r0 < n) ? g_list_w[e * T_TOK + r0] : 0.f;
        float w1 = (r1 < n) ? g_list_w[e * T_TOK + r1] : 0.f;
#pragma unroll
        for (int t = 0; t < 4; t++) {
            int col = c0 + wN * 32 + t * 8 + 2 * tq;
            if (r0 < n) {
                float ox = silu_f(cg[mi][t][0]) * cu[mi][t][0] * w0;
                float oy = silu_f(cg[mi][t][1]) * cu[mi][t][1] * w0;
                *(__half2*)&g_act[((size_t)(off + r0)) * I_DIM + col] = __floats2half2_rn(ox, oy);
            }
            if (r1 < n) {
                float ox = silu_f(cg[mi][t][2]) * cu[mi][t][2] * w1;
                float oy = silu_f(cg[mi][t][3]) * cu[mi][t][3] * w1;
                *(__half2*)&g_act[((size_t)(off + r1)) * I_DIM + col] = __floats2half2_rn(ox, oy);
            }
        }
    }

    // completion flag: all stores visible, then count this tile
    __syncthreads();
    if (tid == 0) { __threadfence(); atomicAdd(&g_done[e], 1); }
}

// ---------------- down tile (BN=128) ----------------
__device__ void do_down(int e, int m0, int c0, const float* __restrict__ dw) {
    int n = g_cnt[e];
    int tid = threadIdx.x;
    if (m0 >= n) return;

    // wait for all gateup tiles of this expert
    if (tid == 0) {
        while (atomicAdd(&g_done[e], 0) < GU_PER_E) __nanosleep(64);
        __threadfence();
    }
    __syncthreads();

    int off = g_off[e];
    uint32_t sbase = smem_u32(dsm);
    int lane = tid & 31;
    int warp = tid >> 5;
    int wM = warp & 3;
    int wN = warp >> 2;

    int lr = tid >> 1;
    int hf = tid & 1;
    const __half* pA = g_act + (size_t)(off + min(m0 + lr, n - 1)) * I_DIM + hf * 16;
    uint32_t soA = lr * RSB + hf * 32;

    const float* pB[2];
    uint32_t soBd[2];
#pragma unroll
    for (int j = 0; j < 2; j++) {
        int c = tid + 256 * j;
        int row = c >> 2;
        pB[j]   = dw + ((size_t)e * H_DIM + (c0 + row)) * I_DIM + (c & 3) * 8;
        soBd[j] = row * RSB + (c & 3) * 16;
    }

    int mat = lane >> 3, rr = lane & 7;
    uint32_t aBase[2], bBase[4];
#pragma unroll
    for (int mi = 0; mi < 2; mi++)
        aBase[mi] = sbase + (uint32_t)((wM * 32 + mi * 16 + (mat & 1) * 8 + rr) * RSB + (mat >> 1) * 16);
#pragma unroll
    for (int p = 0; p < 4; p++)
        bBase[p] = sbase + (uint32_t)((wN * 64 + p * 16 + (mat >> 1) * 8 + rr) * RSB + (mat & 1) * 16);

    float c[2][8][4] = {};

#define DN_A_PAIR(pr)                                                         \
    { int s0_ = 2 * (pr), s1_ = s0_ + 1;                                      \
      uint32_t b0_ = (uint32_t)(s0_ % ASTAGES) * A_STG;                       \
      uint32_t b1_ = (uint32_t)(s1_ % ASTAGES) * A_STG;                       \
      const __half* a0_ = pA + s0_ * 32;                                      \
      const __half* a1_ = pA + s1_ * 32;                                      \
      CP16(sbase + b0_ + soA, a0_); CP16(sbase + b0_ + soA + 16, a0_ + 8);    \
      CP16(sbase + b1_ + soA, a1_); CP16(sbase + b1_ + soA + 16, a1_ + 8); }

#define DN_COMP(astOff, bOff)                                                 \
    { _Pragma("unroll")                                                       \
      for (int ks = 0; ks < 2; ks++) {                                        \
        uint32_t af[2][4];                                                    \
        _Pragma("unroll")                                                     \
        for (int mi = 0; mi < 2; mi++)                                        \
            LDM4(af[mi][0], af[mi][1], af[mi][2], af[mi][3], aBase[mi] + (astOff) + ks * 32); \
        uint32_t bf[4][4];                                                    \
        _Pragma("unroll")                                                     \
        for (int p = 0; p < 4; p++)                                           \
            LDM4(bf[p][0], bf[p][1], bf[p][2], bf[p][3], bBase[p] + (bOff) + ks * 32); \
        _Pragma("unroll")                                                     \
        for (int t = 0; t < 8; t++) {                                         \
            int p = t >> 1, q = (t & 1) * 2;                                  \
            _Pragma("unroll")                                                 \
            for (int mi = 0; mi < 2; mi++)                                    \
                mma16(c[mi][t], af[mi][0], af[mi][1], af[mi][2], af[mi][3], bf[p][q], bf[p][q + 1]); \
        }                                                                     \
      } }

    DN_A_PAIR(0); CP_COMMIT();
    DN_A_PAIR(1); CP_COMMIT();
    {
        float4 a0 = *(const float4*)(pB[0]);
        float4 a1 = *(const float4*)(pB[0] + 4);
        float4 b0 = *(const float4*)(pB[1]);
        float4 b1 = *(const float4*)(pB[1] + 4);
        cvt_sts(dsm + DN_DEST + soBd[0], a0, a1);
        cvt_sts(dsm + DN_DEST + soBd[1], b0, b1);
        const float* q0 = pB[0] + 32;
        const float* q1 = pB[1] + 32;
        a0 = *(const float4*)(q0); a1 = *(const float4*)(q0 + 4);
        b0 = *(const float4*)(q1); b1 = *(const float4*)(q1 + 4);
        cvt_sts(dsm + DN_DEST + DN_SLABB + soBd[0], a0, a1);
        cvt_sts(dsm + DN_DEST + DN_SLABB + soBd[1], b0, b1);
    }

    for (int j = 0; j < DN_NP; j++) {
        CP_WAIT(1);
        __syncthreads();
        uint32_t pbr = DN_DEST + (uint32_t)(j & 1) * DN_PBUF;
        uint32_t pbw = DN_DEST + (uint32_t)((j + 1) & 1) * DN_PBUF;
        int s0 = 2 * j;
        int sn0 = s0 + 2, sn1 = s0 + 3;
        bool hn = (j + 1 < DN_NP);

        float4 na, nb, nc2, nd;
        if (hn) {
            const float* q0 = pB[0] + sn0 * 32;
            const float* q1 = pB[1] + sn0 * 32;
            na = *(const float4*)(q0); nb = *(const float4*)(q0 + 4);
            nc2 = *(const float4*)(q1); nd = *(const float4*)(q1 + 4);
        }

        DN_COMP((uint32_t)(s0 % ASTAGES) * A_STG, pbr);

        if (hn) {
            cvt_sts(dsm + pbw + soBd[0], na, nb);
            cvt_sts(dsm + pbw + soBd[1], nc2, nd);
            const float* q0 = pB[0] + sn1 * 32;
            const float* q1 = pB[1] + sn1 * 32;
            na = *(const float4*)(q0); nb = *(const float4*)(q0 + 4);
            nc2 = *(const float4*)(q1); nd = *(const float4*)(q1 + 4);
        }

        DN_COMP((uint32_t)((s0 + 1) % ASTAGES) * A_STG, pbr + DN_SLABB);

        if (hn) {
            cvt_sts(dsm + pbw + DN_SLABB + soBd[0], na, nb);
            cvt_sts(dsm + pbw + DN_SLABB + soBd[1], nc2, nd);
        }
        if (j + 2 < DN_NP) DN_A_PAIR(j + 2);
        CP_COMMIT();
    }
#undef DN_A_PAIR
#undef DN_COMP

    int g  = lane >> 2;
    int tq = lane & 3;
#pragma unroll
    for (int mi = 0; mi < 2; mi++) {
        int r0 = m0 + wM * 32 + mi * 16 + g;
        int r1 = r0 + 8;
#pragma unroll
        for (int t = 0; t < 8; t++) {
            int col = c0 + wN * 64 + t * 8 + 2 * tq;
            if (r0 < n)
                *(__half2*)&g_pair[((size_t)(off + r0)) * H_DIM + col] =
                    __floats2half2_rn(c[mi][t][0], c[mi][t][1]);
            if (r1 < n)
                *(__half2*)&g_pair[((size_t)(off + r1)) * H_DIM + col] =
                    __floats2half2_rn(c[mi][t][2], c[mi][t][3]);
        }
    }
}

// ---------------- persistent fused MoE kernel ----------------
__global__ __launch_bounds__(256, 2) void moe_kernel(const float* __restrict__ gw,
                                                     const float* __restrict__ uw,
                                                     const float* __restrict__ dw) {
    __shared__ int s_item;
    for (;;) {
        if (threadIdx.x == 0) s_item = atomicAdd(&g_work, 1);
        __syncthreads();
        int item = s_item;
        __syncthreads();
        if (item >= TOT_ITEMS) return;

        if (item < GU_ITEMS) {
            int e = item / GU_PER_E;
            int r = item % GU_PER_E;
            int mx = r & (GU_XT - 1);
            int y  = r >> 3;
            do_gateup(e, mx * BM, y * BN, gw, uw);
        } else {
            int it = item - GU_ITEMS;
            int e = it / DN_PER_E;
            int r = it % DN_PER_E;
            int mx = r & (GU_XT - 1);
            int y  = r >> 3;
            do_down(e, mx * BM, y * DN_BN, dw);
        }
    }
}

// ---------------- per-token reduction (fp16 pairs -> fp32 out) ----------------
__global__ void reduce_kernel(float* __restrict__ out) {
    int t = blockIdx.x;
    int s[K_TOP];
#pragma unroll
    for (int k = 0; k < K_TOP; k++) s[k] = g_slot_of[t * K_TOP + k];
    int i = threadIdx.x;
    float acc[8] = {};
#pragma unroll
    for (int k = 0; k < K_TOP; k++) {
        uint4 v = *(const uint4*)&g_pair[(size_t)s[k] * H_DIM + i * 8];
        const __half2* h = (const __half2*)&v;
#pragma unroll
        for (int q = 0; q < 4; q++) {
            float2 f = __half22float2(h[q]);
            acc[2 * q]     += f.x;
            acc[2 * q + 1] += f.y;
        }
    }
    float4* ob = (float4*)(out + (size_t)t * H_DIM + i * 8);
    ob[0] = make_float4(acc[0], acc[1], acc[2], acc[3]);
    ob[1] = make_float4(acc[4], acc[5], acc[6], acc[7]);
}

// ---------------- launch ----------------
extern "C" void kernel_launch(void* const* d_in, const int* in_sizes, int n_in,
                              void* d_out, int out_size) {
    const float* x      = (const float*)d_in[0];
    const float* gate_w = (const float*)d_in[1];
    const float* gw     = (const float*)d_in[2];
    const float* uw     = (const float*)d_in[3];
    const float* dw     = (const float*)d_in[4];
    float* out = (float*)d_out;

    float* logits = (out_size >= T_TOK * H_DIM + T_TOK * E_NUM) ? (out + (size_t)T_TOK * H_DIM)
                                                                : (float*)0;

    cudaFuncSetAttribute(moe_kernel, cudaFuncAttributeMaxDynamicSharedMemorySize, MOE_SMEM);

    zero_cnt_kernel<<<1, 32>>>();
    router_kernel<<<T_TOK / 4, 256>>>(x, gate_w, logits);
    scan_remap_kernel<<<1, 256>>>();
    moe_kernel<<<304, 256, MOE_SMEM>>>(gw, uw, dw);
    reduce_kernel<<<T_TOK, 256>>>(out);
}